// round 3
// baseline (speedup 1.0000x reference)
#include <cuda_runtime.h>
#include <math.h>

#define Tn 1024
#define Hn 16
#define Dn 64
#define BHn 32
#define NCH 16
#define LCH 64

__device__ float g_q [BHn*Tn*Dn];
__device__ float g_k [BHn*Tn*Dn];
__device__ float g_v [BHn*Tn*Dn];
__device__ float g_ys[BHn*Tn*Dn];
__device__ float g_yl[BHn*Tn*Dn];
__device__ float g_st[BHn*NCH*Dn*Dn];
__device__ float g_ks[BHn*NCH*Dn];

__device__ __forceinline__ float elup(float x){ return x>0.f? x+1.f : __expf(x); }

// ---------------- K1: QKV GEMM -----------------
__global__ __launch_bounds__(256) void k_qkv(const float* __restrict__ x,
                                             const float* __restrict__ w,
                                             const float* __restrict__ bias)
{
    __shared__ __align__(16) float As[16*128];
    __shared__ __align__(16) float Bs[16*128];
    const int tid=threadIdx.x, m0=blockIdx.y*128, n0=blockIdx.x*128;
    const int tx=tid&15, ty=tid>>4;
    float acc[2][2][4][4];
    #pragma unroll
    for(int a=0;a<2;a++) for(int b=0;b<2;b++) for(int i=0;i<4;i++) for(int j=0;j<4;j++) acc[a][b][i][j]=0.f;

    for(int k0=0;k0<1024;k0+=16){
        #pragma unroll
        for(int it=0;it<2;it++){
            int f=it*256+tid, m=f>>2, kq=(f&3)<<2;
            float4 va=*(const float4*)&x[(size_t)(m0+m)*1024+k0+kq];
            As[(kq+0)*128+m]=va.x; As[(kq+1)*128+m]=va.y; As[(kq+2)*128+m]=va.z; As[(kq+3)*128+m]=va.w;
            float4 vb=*(const float4*)&w[(size_t)(n0+m)*1024+k0+kq];
            Bs[(kq+0)*128+m]=vb.x; Bs[(kq+1)*128+m]=vb.y; Bs[(kq+2)*128+m]=vb.z; Bs[(kq+3)*128+m]=vb.w;
        }
        __syncthreads();
        #pragma unroll
        for(int kk=0;kk<16;kk++){
            float a[2][4], bb[2][4];
            *(float4*)a[0]=*(const float4*)&As[kk*128+ty*4];
            *(float4*)a[1]=*(const float4*)&As[kk*128+64+ty*4];
            *(float4*)bb[0]=*(const float4*)&Bs[kk*128+tx*4];
            *(float4*)bb[1]=*(const float4*)&Bs[kk*128+64+tx*4];
            #pragma unroll
            for(int qi=0;qi<2;qi++) for(int qj=0;qj<2;qj++)
                for(int i=0;i<4;i++) for(int j=0;j<4;j++)
                    acc[qi][qj][i][j]+=a[qi][i]*bb[qj][j];
        }
        __syncthreads();
    }
    const int sect=n0>>10;
    float* outp = sect==0? g_q : (sect==1? g_k : g_v);
    const int nc0=n0&1023;
    #pragma unroll
    for(int qi=0;qi<2;qi++) for(int i=0;i<4;i++){
        int m=m0+qi*64+ty*4+i, b=m>>10, t=m&1023;
        #pragma unroll
        for(int qj=0;qj<2;qj++) for(int j=0;j<4;j++){
            int col=qj*64+tx*4+j, cc=nc0+col, h=cc>>6, d=cc&63;
            outp[(((size_t)(b*Hn+h))*Tn+t)*Dn+d]=acc[qi][qj][i][j]+bias[n0+col];
        }
    }
}

// ---------------- K2: causal softmax attention -----------------
__global__ __launch_bounds__(256) void k_attn()
{
    __shared__ __align__(16) float qs[64*64];
    __shared__ float ks[32*65];
    __shared__ __align__(16) float vs[32*64];
    __shared__ float ps[64*33];
    __shared__ float rs_sh[64], l_sh[64];
    const int tid=threadIdx.x, qi=blockIdx.x, bh=blockIdx.y, q0=qi*64;
    const float* qb=g_q+(size_t)bh*Tn*Dn;
    const float* kb=g_k+(size_t)bh*Tn*Dn;
    const float* vb=g_v+(size_t)bh*Tn*Dn;
    #pragma unroll
    for(int it=0;it<4;it++){
        int f=it*256+tid, t=f>>4, d4=(f&15)<<2;
        *(float4*)&qs[t*64+d4]=*(const float4*)&qb[(size_t)(q0+t)*64+d4];
    }
    const int tx=tid&15, ty=tid>>4, txs=tid&7, tys=tid>>3;
    float o[4][4];
    #pragma unroll
    for(int i=0;i<4;i++) for(int j=0;j<4;j++) o[i][j]=0.f;
    float m_r=-1e30f, l_r=0.f;
    const int nkt=2*qi+2;
    for(int kt=0;kt<nkt;kt++){
        const int k0=kt*32;
        __syncthreads();
        #pragma unroll
        for(int it=0;it<2;it++){
            int f=it*256+tid, s=f>>4, d4=(f&15)<<2;
            float4 k4=*(const float4*)&kb[(size_t)(k0+s)*64+d4];
            ks[s*65+d4]=k4.x; ks[s*65+d4+1]=k4.y; ks[s*65+d4+2]=k4.z; ks[s*65+d4+3]=k4.w;
            *(float4*)&vs[s*64+d4]=*(const float4*)&vb[(size_t)(k0+s)*64+d4];
        }
        __syncthreads();
        float sa[2][4];
        #pragma unroll
        for(int i=0;i<2;i++) for(int j=0;j<4;j++) sa[i][j]=0.f;
        #pragma unroll 8
        for(int d=0;d<64;d++){
            float a0=qs[(tys*2+0)*64+d], a1=qs[(tys*2+1)*64+d];
            float b0=ks[(txs*4+0)*65+d], b1=ks[(txs*4+1)*65+d];
            float b2=ks[(txs*4+2)*65+d], b3=ks[(txs*4+3)*65+d];
            sa[0][0]+=a0*b0; sa[0][1]+=a0*b1; sa[0][2]+=a0*b2; sa[0][3]+=a0*b3;
            sa[1][0]+=a1*b0; sa[1][1]+=a1*b1; sa[1][2]+=a1*b2; sa[1][3]+=a1*b3;
        }
        const bool mk=(kt>=2*qi);
        #pragma unroll
        for(int i=0;i<2;i++) for(int j=0;j<4;j++){
            float sv=sa[i][j]*0.125f;
            if(mk && (k0+txs*4+j > q0+tys*2+i)) sv=-1e30f;
            ps[(tys*2+i)*33+txs*4+j]=sv;
        }
        __syncthreads();
        if(tid<64){
            float ml=-1e30f;
            #pragma unroll 8
            for(int s=0;s<32;s++) ml=fmaxf(ml,ps[tid*33+s]);
            float mn=fmaxf(m_r,ml), corr=__expf(m_r-mn), ls=0.f;
            #pragma unroll 8
            for(int s=0;s<32;s++){ float p=__expf(ps[tid*33+s]-mn); ps[tid*33+s]=p; ls+=p; }
            l_r=l_r*corr+ls; m_r=mn; rs_sh[tid]=corr;
        }
        __syncthreads();
        float r0=rs_sh[ty*4], r1=rs_sh[ty*4+1], r2=rs_sh[ty*4+2], r3=rs_sh[ty*4+3];
        #pragma unroll
        for(int j=0;j<4;j++){ o[0][j]*=r0; o[1][j]*=r1; o[2][j]*=r2; o[3][j]*=r3; }
        #pragma unroll 8
        for(int s=0;s<32;s++){
            float a0=ps[(ty*4+0)*33+s], a1=ps[(ty*4+1)*33+s];
            float a2=ps[(ty*4+2)*33+s], a3=ps[(ty*4+3)*33+s];
            float b0=vs[s*64+tx*4], b1=vs[s*64+tx*4+1], b2=vs[s*64+tx*4+2], b3=vs[s*64+tx*4+3];
            o[0][0]+=a0*b0; o[0][1]+=a0*b1; o[0][2]+=a0*b2; o[0][3]+=a0*b3;
            o[1][0]+=a1*b0; o[1][1]+=a1*b1; o[1][2]+=a1*b2; o[1][3]+=a1*b3;
            o[2][0]+=a2*b0; o[2][1]+=a2*b1; o[2][2]+=a2*b2; o[2][3]+=a2*b3;
            o[3][0]+=a3*b0; o[3][1]+=a3*b1; o[3][2]+=a3*b2; o[3][3]+=a3*b3;
        }
    }
    if(tid<64) l_sh[tid]=l_r;
    __syncthreads();
    float* yb=g_ys+(size_t)bh*Tn*Dn;
    #pragma unroll
    for(int i=0;i<4;i++){
        float inv=1.f/l_sh[ty*4+i];
        #pragma unroll
        for(int j=0;j<4;j++) yb[(size_t)(q0+ty*4+i)*64+tx*4+j]=o[i][j]*inv;
    }
}

// ---------------- K3a: linear-attn chunk sums -----------------
__global__ __launch_bounds__(256) void k_lchunk()
{
    __shared__ __align__(16) float Kp[64*64];
    __shared__ __align__(16) float vv[64*64];
    const int tid=threadIdx.x, ch=blockIdx.x, bh=blockIdx.y, t0=ch*LCH;
    const float* kb=g_k+(size_t)bh*Tn*Dn;
    const float* vb=g_v+(size_t)bh*Tn*Dn;
    #pragma unroll
    for(int it=0;it<4;it++){
        int f=it*256+tid, t=f>>4, d4=(f&15)<<2;
        float4 k4=*(const float4*)&kb[(size_t)(t0+t)*64+d4];
        float4 kp; kp.x=elup(k4.x*0.125f); kp.y=elup(k4.y*0.125f); kp.z=elup(k4.z*0.125f); kp.w=elup(k4.w*0.125f);
        *(float4*)&Kp[t*64+d4]=kp;
        *(float4*)&vv[t*64+d4]=*(const float4*)&vb[(size_t)(t0+t)*64+d4];
    }
    __syncthreads();
    const int tx=tid&15, ty=tid>>4;
    float acc[4][4];
    #pragma unroll
    for(int i=0;i<4;i++) for(int j=0;j<4;j++) acc[i][j]=0.f;
    #pragma unroll 8
    for(int t=0;t<64;t++){
        float a0=Kp[t*64+ty*4], a1=Kp[t*64+ty*4+1], a2=Kp[t*64+ty*4+2], a3=Kp[t*64+ty*4+3];
        float b0=vv[t*64+tx*4], b1=vv[t*64+tx*4+1], b2=vv[t*64+tx*4+2], b3=vv[t*64+tx*4+3];
        acc[0][0]+=a0*b0; acc[0][1]+=a0*b1; acc[0][2]+=a0*b2; acc[0][3]+=a0*b3;
        acc[1][0]+=a1*b0; acc[1][1]+=a1*b1; acc[1][2]+=a1*b2; acc[1][3]+=a1*b3;
        acc[2][0]+=a2*b0; acc[2][1]+=a2*b1; acc[2][2]+=a2*b2; acc[2][3]+=a2*b3;
        acc[3][0]+=a3*b0; acc[3][1]+=a3*b1; acc[3][2]+=a3*b2; acc[3][3]+=a3*b3;
    }
    float* st=g_st+(size_t)(bh*NCH+ch)*4096;
    #pragma unroll
    for(int i=0;i<4;i++) for(int j=0;j<4;j++) st[(ty*4+i)*64+tx*4+j]=acc[i][j];
    if(tid<64){
        float s=0.f;
        #pragma unroll 8
        for(int t=0;t<64;t++) s+=Kp[t*64+tid];
        g_ks[(bh*NCH+ch)*64+tid]=s;
    }
}

// ---------------- K3b: exclusive scan over chunks -----------------
__global__ __launch_bounds__(256) void k_lscan()
{
    const int bh=blockIdx.x, tid=threadIdx.x;
    for(int e=tid;e<4096;e+=256){
        float run=0.f;
        #pragma unroll
        for(int ch=0;ch<NCH;ch++){
            float* p=&g_st[(size_t)(bh*NCH+ch)*4096+e];
            float tv=*p; *p=run; run+=tv;
        }
    }
    if(tid<64){
        float run=0.f;
        #pragma unroll
        for(int ch=0;ch<NCH;ch++){
            float* p=&g_ks[(bh*NCH+ch)*64+tid];
            float tv=*p; *p=run; run+=tv;
        }
    }
}

// ---------------- K3c: linear-attn output -----------------
__global__ __launch_bounds__(256) void k_lout()
{
    __shared__ __align__(16) float bufQ[64*64];
    __shared__ float bufA[64*65];
    __shared__ float ks0[64], den[64];
    const int tid=threadIdx.x, ch=blockIdx.x, bh=blockIdx.y, t0=ch*LCH;
    const int tx=tid&15, ty=tid>>4;
    const float* qb=g_q+(size_t)bh*Tn*Dn;
    const float* kb=g_k+(size_t)bh*Tn*Dn;
    const float* vb=g_v+(size_t)bh*Tn*Dn;
    const float* S0=g_st+(size_t)(bh*NCH+ch)*4096;
    #pragma unroll
    for(int it=0;it<4;it++){
        int f=it*256+tid, t=f>>4, d4=(f&15)<<2;
        float4 q4=*(const float4*)&qb[(size_t)(t0+t)*64+d4];
        float4 qp; qp.x=elup(q4.x*0.125f); qp.y=elup(q4.y*0.125f); qp.z=elup(q4.z*0.125f); qp.w=elup(q4.w*0.125f);
        *(float4*)&bufQ[t*64+d4]=qp;
        float4 k4=*(const float4*)&kb[(size_t)(t0+t)*64+d4];
        bufA[t*65+d4]=elup(k4.x*0.125f); bufA[t*65+d4+1]=elup(k4.y*0.125f);
        bufA[t*65+d4+2]=elup(k4.z*0.125f); bufA[t*65+d4+3]=elup(k4.w*0.125f);
    }
    if(tid<64) ks0[tid]=g_ks[(bh*NCH+ch)*64+tid];
    __syncthreads();
    // A[t][s] = Qp.Kp masked, and y_inter = Qp @ S0
    float A4[4][4], o[4][4];
    #pragma unroll
    for(int i=0;i<4;i++) for(int j=0;j<4;j++){ A4[i][j]=0.f; o[i][j]=0.f; }
    #pragma unroll 4
    for(int d=0;d<64;d++){
        float a0=bufQ[(ty*4+0)*64+d], a1=bufQ[(ty*4+1)*64+d];
        float a2=bufQ[(ty*4+2)*64+d], a3=bufQ[(ty*4+3)*64+d];
        float b0=bufA[(tx*4+0)*65+d], b1=bufA[(tx*4+1)*65+d];
        float b2=bufA[(tx*4+2)*65+d], b3=bufA[(tx*4+3)*65+d];
        A4[0][0]+=a0*b0; A4[0][1]+=a0*b1; A4[0][2]+=a0*b2; A4[0][3]+=a0*b3;
        A4[1][0]+=a1*b0; A4[1][1]+=a1*b1; A4[1][2]+=a1*b2; A4[1][3]+=a1*b3;
        A4[2][0]+=a2*b0; A4[2][1]+=a2*b1; A4[2][2]+=a2*b2; A4[2][3]+=a2*b3;
        A4[3][0]+=a3*b0; A4[3][1]+=a3*b1; A4[3][2]+=a3*b2; A4[3][3]+=a3*b3;
        float4 s4=*(const float4*)&S0[d*64+tx*4];
        o[0][0]+=a0*s4.x; o[0][1]+=a0*s4.y; o[0][2]+=a0*s4.z; o[0][3]+=a0*s4.w;
        o[1][0]+=a1*s4.x; o[1][1]+=a1*s4.y; o[1][2]+=a1*s4.z; o[1][3]+=a1*s4.w;
        o[2][0]+=a2*s4.x; o[2][1]+=a2*s4.y; o[2][2]+=a2*s4.z; o[2][3]+=a2*s4.w;
        o[3][0]+=a3*s4.x; o[3][1]+=a3*s4.y; o[3][2]+=a3*s4.z; o[3][3]+=a3*s4.w;
    }
    __syncthreads();   // done reading Kp
    #pragma unroll
    for(int i=0;i<4;i++) for(int j=0;j<4;j++){
        int t=ty*4+i, s=tx*4+j;
        bufA[t*65+s] = (s<=t)? A4[i][j] : 0.f;
    }
    __syncthreads();
    if(tid<64){
        float dsum=0.f;
        #pragma unroll 8
        for(int s=0;s<64;s++) dsum+=bufA[tid*65+s];
        #pragma unroll 8
        for(int d=0;d<64;d++) dsum+=bufQ[tid*64+d]*ks0[d];
        den[tid]=dsum;
    }
    // y_intra: o += A @ V  (V from gmem)
    #pragma unroll 4
    for(int s=0;s<64;s++){
        float a0=bufA[(ty*4+0)*65+s], a1=bufA[(ty*4+1)*65+s];
        float a2=bufA[(ty*4+2)*65+s], a3=bufA[(ty*4+3)*65+s];
        float4 v4=*(const float4*)&vb[(size_t)(t0+s)*64+tx*4];
        o[0][0]+=a0*v4.x; o[0][1]+=a0*v4.y; o[0][2]+=a0*v4.z; o[0][3]+=a0*v4.w;
        o[1][0]+=a1*v4.x; o[1][1]+=a1*v4.y; o[1][2]+=a1*v4.z; o[1][3]+=a1*v4.w;
        o[2][0]+=a2*v4.x; o[2][1]+=a2*v4.y; o[2][2]+=a2*v4.z; o[2][3]+=a2*v4.w;
        o[3][0]+=a3*v4.x; o[3][1]+=a3*v4.y; o[3][2]+=a3*v4.z; o[3][3]+=a3*v4.w;
    }
    __syncthreads();
    float* yb=g_yl+(size_t)bh*Tn*Dn;
    #pragma unroll
    for(int i=0;i<4;i++){
        float inv=1.f/(den[ty*4+i]+1e-4f);
        #pragma unroll
        for(int j=0;j<4;j++) yb[(size_t)(t0+ty*4+i)*64+tx*4+j]=o[i][j]*inv;
    }
}

// ---------------- K4: epilogue megakernel -----------------
__device__ __forceinline__ void bred2(float& s, float& ss, float* scr, int tid){
    #pragma unroll
    for(int off=16;off>0;off>>=1){
        s += __shfl_xor_sync(0xffffffffu, s, off);
        ss+= __shfl_xor_sync(0xffffffffu, ss, off);
    }
    int w=tid>>5;
    if((tid&31)==0){ scr[w]=s; scr[8+w]=ss; }
    __syncthreads();
    if(tid<8){ s=scr[tid]; ss=scr[8+tid]; }
    else { s=0.f; ss=0.f; }
    if(tid<32){
        #pragma unroll
        for(int off=4;off>0;off>>=1){
            s += __shfl_xor_sync(0xffffffffu, s, off);
            ss+= __shfl_xor_sync(0xffffffffu, ss, off);
        }
        if(tid==0){ scr[16]=s; scr[17]=ss; }
    }
    __syncthreads();
    s=scr[16]; ss=scr[17];
    __syncthreads();
}

__global__ __launch_bounds__(256) void k_epi(
    const float* __restrict__ fg,
    const float* __restrict__ ang, const float* __restrict__ anb,
    const float* __restrict__ ong, const float* __restrict__ onb,
    const float* __restrict__ pg,  const float* __restrict__ pb,
    const float* __restrict__ bw,  const float* __restrict__ wrow,
    const float* __restrict__ wcol,const float* __restrict__ pa_,
    const float* __restrict__ pbias, float* __restrict__ out)
{
    __shared__ float yv[1024];
    __shared__ float xn[1024];
    __shared__ float z[32*33];
    __shared__ float scr[18];
    const int tid=threadIdx.x;
    const int bt=blockIdx.x, b=bt>>10, t=bt&1023;
    const float alpha=1.f/(1.f+__expf(-fg[0]));
    const float pav=pa_[0];
    // per-head LN of y_lin + gate combine
    {
        int h=tid>>4, l=tid&15, d0=l*4;
        size_t base=(((size_t)(b*Hn+h))*Tn+t)*Dn;
        float4 v4=*(const float4*)&g_yl[base+d0];
        float s=v4.x+v4.y+v4.z+v4.w;
        float ss=v4.x*v4.x+v4.y*v4.y+v4.z*v4.z+v4.w*v4.w;
        #pragma unroll
        for(int off=8;off>0;off>>=1){
            s += __shfl_xor_sync(0xffffffffu, s, off, 16);
            ss+= __shfl_xor_sync(0xffffffffu, ss, off, 16);
        }
        float m=s*(1.f/64.f), var=ss*(1.f/64.f)-m*m;
        float rs=rsqrtf(var+1e-5f);
        float4 s4=*(const float4*)&g_ys[base+d0];
        float r[4]={v4.x,v4.y,v4.z,v4.w}, sh[4]={s4.x,s4.y,s4.z,s4.w};
        #pragma unroll
        for(int q=0;q<4;q++){
            float ln=(r[q]-m)*rs*ang[d0+q]+anb[d0+q];
            yv[h*64+d0+q]=alpha*sh[q]+(1.f-alpha)*ln;
        }
    }
    __syncthreads();
    // out LN over 1024
    {
        float s=0.f, ss=0.f;
        #pragma unroll
        for(int q=0;q<4;q++){ float v=yv[tid*4+q]; s+=v; ss+=v*v; }
        bred2(s,ss,scr,tid);
        float m=s*(1.f/1024.f), var=ss*(1.f/1024.f)-m*m, rs=rsqrtf(var+1e-5f);
        #pragma unroll
        for(int q=0;q<4;q++){
            int c=tid*4+q;
            yv[c]=(yv[c]-m)*rs*ong[c]+onb[c];
        }
    }
    __syncthreads();
    // pre LN -> xn
    {
        float s=0.f, ss=0.f;
        #pragma unroll
        for(int q=0;q<4;q++){ float v=yv[tid*4+q]; s+=v; ss+=v*v; }
        bred2(s,ss,scr,tid);
        float m=s*(1.f/1024.f), var=ss*(1.f/1024.f)-m*m, rs=rsqrtf(var+1e-5f);
        #pragma unroll
        for(int q=0;q<4;q++){
            int c=tid*4+q;
            xn[c]=(yv[c]-m)*rs*pg[c]+pb[c];
        }
    }
    __syncthreads();
    // grid z[i][c] = sum_j xn[i*32+j]*wcol[j*32+c]
    #pragma unroll
    for(int q=0;q<4;q++){
        int p=tid*4+q, i=p>>5, c=p&31;
        float acc=0.f;
        #pragma unroll 8
        for(int j=0;j<32;j++) acc+=xn[i*32+j]*wcol[j*32+c];
        z[i*33+c]=acc;
    }
    __syncthreads();
    // outputs
    float* orow=out+(size_t)bt*1024;
    #pragma unroll
    for(int q=0;q<4;q++){
        int p=tid*4+q;
        int mrev=1023-p, gm=mrev>>4, jj=mrev&15;
        float bo=0.f;
        #pragma unroll
        for(int i=0;i<16;i++) bo+=xn[gm*16+i]*bw[(gm*16+i)*16+jj];
        int gi=p>>5, r=p&31;
        float zz=0.f;
        #pragma unroll 8
        for(int c=0;c<32;c++) zz+=z[gi*33+c]*wrow[r*32+c];
        orow[p]=bo+pav*zz+pbias[p];
    }
}

extern "C" void kernel_launch(void* const* d_in, const int* in_sizes, int n_in,
                              void* d_out, int out_size)
{
    const float* x    =(const float*)d_in[0];
    const float* caw  =(const float*)d_in[1];
    const float* cab  =(const float*)d_in[2];
    const float* fg   =(const float*)d_in[3];
    const float* ang  =(const float*)d_in[4];
    const float* anb  =(const float*)d_in[5];
    const float* ong  =(const float*)d_in[6];
    const float* onb  =(const float*)d_in[7];
    const float* ppg  =(const float*)d_in[8];
    const float* ppb  =(const float*)d_in[9];
    const float* pbw  =(const float*)d_in[10];
    const float* pwr  =(const float*)d_in[11];
    const float* pwc  =(const float*)d_in[12];
    const float* pal  =(const float*)d_in[13];
    const float* pbi  =(const float*)d_in[14];
    float* out=(float*)d_out;

    k_qkv<<<dim3(24,16),256>>>(x,caw,cab);
    k_attn<<<dim3(16,32),256>>>();
    k_lchunk<<<dim3(NCH,32),256>>>();
    k_lscan<<<32,256>>>();
    k_lout<<<dim3(NCH,32),256>>>();
    k_epi<<<2048,256>>>(fg,ang,anb,ong,onb,ppg,ppb,pbw,pwr,pwc,pal,pbi,out);
}

// round 6
// speedup vs baseline: 1.3180x; 1.3180x over previous
#include <cuda_runtime.h>
#include <cuda_bf16.h>
#include <math.h>

#define Tn 1024
#define Hn 16
#define Dn 64
#define BHn 32
#define NCH 16
#define LCH 64

__device__ float g_q [BHn*Tn*Dn];
__device__ float g_k [BHn*Tn*Dn];
__device__ float g_v [BHn*Tn*Dn];
__device__ float g_ys[BHn*Tn*Dn];
__device__ float g_yl[BHn*Tn*Dn];
__device__ float g_st[BHn*NCH*Dn*Dn];
__device__ float g_ks[BHn*NCH*Dn];

__device__ __forceinline__ float elup(float x){ return x>0.f? x+1.f : __expf(x); }

__device__ __forceinline__ unsigned pk2(__nv_bfloat16 a, __nv_bfloat16 b){
    __nv_bfloat162 t = __halves2bfloat162(a,b);
    return *(unsigned*)&t;
}
__device__ __forceinline__ void mma16816(float* d, const unsigned* a, const unsigned* b){
    asm volatile("mma.sync.aligned.m16n8k16.row.col.f32.bf16.bf16.f32 "
        "{%0,%1,%2,%3}, {%4,%5,%6,%7}, {%8,%9}, {%0,%1,%2,%3};"
        : "+f"(d[0]),"+f"(d[1]),"+f"(d[2]),"+f"(d[3])
        : "r"(a[0]),"r"(a[1]),"r"(a[2]),"r"(a[3]), "r"(b[0]),"r"(b[1]));
}
#define LDU(arr,idx) (*(const unsigned*)&(arr)[idx])

// ---------------- K1: QKV GEMM (bf16 split-3 tensor-core) -----------------
// qkv[m,n] = sum_k x[m,k]*w[n,k] + bias[n];  M=2048, N=3072, K=1024
#define KT 32
#define LDA 40   // padded row stride in bf16 elems (20 words -> conflict-free)
__global__ __launch_bounds__(256) void k_qkv(const float* __restrict__ x,
                                             const float* __restrict__ w,
                                             const float* __restrict__ bias)
{
    __shared__ __align__(16) __nv_bfloat16 Ah[128*LDA], Al[128*LDA];
    __shared__ __align__(16) __nv_bfloat16 Bh[128*LDA], Bl[128*LDA];
    const int tid=threadIdx.x;
    const int m0=blockIdx.y*128, n0=blockIdx.x*128;
    const int wid=tid>>5, lane=tid&31;
    const int wm=wid&1, wn=wid>>1;          // warp tile (wm*64, wn*32)
    const int g=lane>>2, tg=lane&3;

    float acc[4][4][4];
    #pragma unroll
    for(int a=0;a<4;a++) for(int b=0;b<4;b++) for(int c=0;c<4;c++) acc[a][b][c]=0.f;

    for(int k0=0;k0<1024;k0+=KT){
        #pragma unroll
        for(int it=0;it<4;it++){
            int f=it*256+tid, r=f>>3, c4=f&7;
            float4 va=*(const float4*)&x[(size_t)(m0+r)*1024+k0+c4*4];
            __nv_bfloat16 h0=__float2bfloat16(va.x), h1=__float2bfloat16(va.y);
            __nv_bfloat16 h2=__float2bfloat16(va.z), h3=__float2bfloat16(va.w);
            __nv_bfloat16 l0=__float2bfloat16(va.x-__bfloat162float(h0));
            __nv_bfloat16 l1=__float2bfloat16(va.y-__bfloat162float(h1));
            __nv_bfloat16 l2=__float2bfloat16(va.z-__bfloat162float(h2));
            __nv_bfloat16 l3=__float2bfloat16(va.w-__bfloat162float(h3));
            *(uint2*)&Ah[r*LDA+c4*4]=make_uint2(pk2(h0,h1),pk2(h2,h3));
            *(uint2*)&Al[r*LDA+c4*4]=make_uint2(pk2(l0,l1),pk2(l2,l3));
            float4 vb=*(const float4*)&w[(size_t)(n0+r)*1024+k0+c4*4];
            h0=__float2bfloat16(vb.x); h1=__float2bfloat16(vb.y);
            h2=__float2bfloat16(vb.z); h3=__float2bfloat16(vb.w);
            l0=__float2bfloat16(vb.x-__bfloat162float(h0));
            l1=__float2bfloat16(vb.y-__bfloat162float(h1));
            l2=__float2bfloat16(vb.z-__bfloat162float(h2));
            l3=__float2bfloat16(vb.w-__bfloat162float(h3));
            *(uint2*)&Bh[r*LDA+c4*4]=make_uint2(pk2(h0,h1),pk2(h2,h3));
            *(uint2*)&Bl[r*LDA+c4*4]=make_uint2(pk2(l0,l1),pk2(l2,l3));
        }
        __syncthreads();
        #pragma unroll
        for(int ks=0;ks<KT;ks+=16){
            unsigned ah[4][4], al[4][4], bh[4][2], bl[4][2];
            #pragma unroll
            for(int mi=0;mi<4;mi++){
                int r0=(wm*64+mi*16+g)*LDA + ks + 2*tg;
                int r1=r0 + 8*LDA;
                ah[mi][0]=LDU(Ah,r0); ah[mi][1]=LDU(Ah,r1);
                ah[mi][2]=LDU(Ah,r0+8); ah[mi][3]=LDU(Ah,r1+8);
                al[mi][0]=LDU(Al,r0); al[mi][1]=LDU(Al,r1);
                al[mi][2]=LDU(Al,r0+8); al[mi][3]=LDU(Al,r1+8);
            }
            #pragma unroll
            for(int nj=0;nj<4;nj++){
                int rn=(wn*32+nj*8+g)*LDA + ks + 2*tg;
                bh[nj][0]=LDU(Bh,rn); bh[nj][1]=LDU(Bh,rn+8);
                bl[nj][0]=LDU(Bl,rn); bl[nj][1]=LDU(Bl,rn+8);
            }
            #pragma unroll
            for(int mi=0;mi<4;mi++)
            #pragma unroll
            for(int nj=0;nj<4;nj++){
                mma16816(acc[mi][nj], ah[mi], bh[nj]);
                mma16816(acc[mi][nj], ah[mi], bl[nj]);
                mma16816(acc[mi][nj], al[mi], bh[nj]);
            }
        }
        __syncthreads();
    }
    const int sect=n0>>10;
    float* outp = sect==0? g_q : (sect==1? g_k : g_v);
    const int nc0=n0&1023;
    #pragma unroll
    for(int mi=0;mi<4;mi++){
        int mr=m0+wm*64+mi*16+g;
        #pragma unroll
        for(int half=0;half<2;half++){
            int m=mr+half*8, b=m>>10, t=m&1023;
            #pragma unroll
            for(int nj=0;nj<4;nj++){
                int off=wn*32+nj*8+2*tg;
                int cc=nc0+off, h=cc>>6, d=cc&63;
                int gn=n0+off;
                float2 o2;
                o2.x=acc[mi][nj][half*2+0]+bias[gn];
                o2.y=acc[mi][nj][half*2+1]+bias[gn+1];
                *(float2*)&outp[(((size_t)(b*Hn+h))*Tn+t)*Dn+d]=o2;
            }
        }
    }
}

// ---------------- K2: causal softmax attention -----------------
__global__ __launch_bounds__(256) void k_attn()
{
    __shared__ __align__(16) float qs[64*64];
    __shared__ float ks[32*65];
    __shared__ __align__(16) float vs[32*64];
    __shared__ float ps[64*33];
    __shared__ float rs_sh[64], l_sh[64];
    const int tid=threadIdx.x, qi=blockIdx.x, bh=blockIdx.y, q0=qi*64;
    const float* qb=g_q+(size_t)bh*Tn*Dn;
    const float* kb=g_k+(size_t)bh*Tn*Dn;
    const float* vb=g_v+(size_t)bh*Tn*Dn;
    #pragma unroll
    for(int it=0;it<4;it++){
        int f=it*256+tid, t=f>>4, d4=(f&15)<<2;
        *(float4*)&qs[t*64+d4]=*(const float4*)&qb[(size_t)(q0+t)*64+d4];
    }
    const int tx=tid&15, ty=tid>>4, txs=tid&7, tys=tid>>3;
    float o[4][4];
    #pragma unroll
    for(int i=0;i<4;i++) for(int j=0;j<4;j++) o[i][j]=0.f;
    float m_r=-1e30f, l_r=0.f;
    const int nkt=2*qi+2;
    for(int kt=0;kt<nkt;kt++){
        const int k0=kt*32;
        __syncthreads();
        #pragma unroll
        for(int it=0;it<2;it++){
            int f=it*256+tid, s=f>>4, d4=(f&15)<<2;
            float4 k4=*(const float4*)&kb[(size_t)(k0+s)*64+d4];
            ks[s*65+d4]=k4.x; ks[s*65+d4+1]=k4.y; ks[s*65+d4+2]=k4.z; ks[s*65+d4+3]=k4.w;
            *(float4*)&vs[s*64+d4]=*(const float4*)&vb[(size_t)(k0+s)*64+d4];
        }
        __syncthreads();
        float sa[2][4];
        #pragma unroll
        for(int i=0;i<2;i++) for(int j=0;j<4;j++) sa[i][j]=0.f;
        #pragma unroll 8
        for(int d=0;d<64;d++){
            float a0=qs[(tys*2+0)*64+d], a1=qs[(tys*2+1)*64+d];
            float b0=ks[(txs*4+0)*65+d], b1=ks[(txs*4+1)*65+d];
            float b2=ks[(txs*4+2)*65+d], b3=ks[(txs*4+3)*65+d];
            sa[0][0]+=a0*b0; sa[0][1]+=a0*b1; sa[0][2]+=a0*b2; sa[0][3]+=a0*b3;
            sa[1][0]+=a1*b0; sa[1][1]+=a1*b1; sa[1][2]+=a1*b2; sa[1][3]+=a1*b3;
        }
        const bool mk=(kt>=2*qi);
        #pragma unroll
        for(int i=0;i<2;i++) for(int j=0;j<4;j++){
            float sv=sa[i][j]*0.125f;
            if(mk && (k0+txs*4+j > q0+tys*2+i)) sv=-1e30f;
            ps[(tys*2+i)*33+txs*4+j]=sv;
        }
        __syncthreads();
        if(tid<64){
            float ml=-1e30f;
            #pragma unroll 8
            for(int s=0;s<32;s++) ml=fmaxf(ml,ps[tid*33+s]);
            float mn=fmaxf(m_r,ml), corr=__expf(m_r-mn), ls=0.f;
            #pragma unroll 8
            for(int s=0;s<32;s++){ float p=__expf(ps[tid*33+s]-mn); ps[tid*33+s]=p; ls+=p; }
            l_r=l_r*corr+ls; m_r=mn; rs_sh[tid]=corr;
        }
        __syncthreads();
        float r0=rs_sh[ty*4], r1=rs_sh[ty*4+1], r2=rs_sh[ty*4+2], r3=rs_sh[ty*4+3];
        #pragma unroll
        for(int j=0;j<4;j++){ o[0][j]*=r0; o[1][j]*=r1; o[2][j]*=r2; o[3][j]*=r3; }
        #pragma unroll 8
        for(int s=0;s<32;s++){
            float a0=ps[(ty*4+0)*33+s], a1=ps[(ty*4+1)*33+s];
            float a2=ps[(ty*4+2)*33+s], a3=ps[(ty*4+3)*33+s];
            float b0=vs[s*64+tx*4], b1=vs[s*64+tx*4+1], b2=vs[s*64+tx*4+2], b3=vs[s*64+tx*4+3];
            o[0][0]+=a0*b0; o[0][1]+=a0*b1; o[0][2]+=a0*b2; o[0][3]+=a0*b3;
            o[1][0]+=a1*b0; o[1][1]+=a1*b1; o[1][2]+=a1*b2; o[1][3]+=a1*b3;
            o[2][0]+=a2*b0; o[2][1]+=a2*b1; o[2][2]+=a2*b2; o[2][3]+=a2*b3;
            o[3][0]+=a3*b0; o[3][1]+=a3*b1; o[3][2]+=a3*b2; o[3][3]+=a3*b3;
        }
    }
    if(tid<64) l_sh[tid]=l_r;
    __syncthreads();
    float* yb=g_ys+(size_t)bh*Tn*Dn;
    #pragma unroll
    for(int i=0;i<4;i++){
        float inv=1.f/l_sh[ty*4+i];
        #pragma unroll
        for(int j=0;j<4;j++) yb[(size_t)(q0+ty*4+i)*64+tx*4+j]=o[i][j]*inv;
    }
}

// ---------------- K3a: linear-attn chunk sums -----------------
__global__ __launch_bounds__(256) void k_lchunk()
{
    __shared__ __align__(16) float Kp[64*64];
    __shared__ __align__(16) float vv[64*64];
    const int tid=threadIdx.x, ch=blockIdx.x, bh=blockIdx.y, t0=ch*LCH;
    const float* kb=g_k+(size_t)bh*Tn*Dn;
    const float* vb=g_v+(size_t)bh*Tn*Dn;
    #pragma unroll
    for(int it=0;it<4;it++){
        int f=it*256+tid, t=f>>4, d4=(f&15)<<2;
        float4 k4=*(const float4*)&kb[(size_t)(t0+t)*64+d4];
        float4 kp; kp.x=elup(k4.x*0.125f); kp.y=elup(k4.y*0.125f); kp.z=elup(k4.z*0.125f); kp.w=elup(k4.w*0.125f);
        *(float4*)&Kp[t*64+d4]=kp;
        *(float4*)&vv[t*64+d4]=*(const float4*)&vb[(size_t)(t0+t)*64+d4];
    }
    __syncthreads();
    const int tx=tid&15, ty=tid>>4;
    float acc[4][4];
    #pragma unroll
    for(int i=0;i<4;i++) for(int j=0;j<4;j++) acc[i][j]=0.f;
    #pragma unroll 8
    for(int t=0;t<64;t++){
        float a0=Kp[t*64+ty*4], a1=Kp[t*64+ty*4+1], a2=Kp[t*64+ty*4+2], a3=Kp[t*64+ty*4+3];
        float b0=vv[t*64+tx*4], b1=vv[t*64+tx*4+1], b2=vv[t*64+tx*4+2], b3=vv[t*64+tx*4+3];
        acc[0][0]+=a0*b0; acc[0][1]+=a0*b1; acc[0][2]+=a0*b2; acc[0][3]+=a0*b3;
        acc[1][0]+=a1*b0; acc[1][1]+=a1*b1; acc[1][2]+=a1*b2; acc[1][3]+=a1*b3;
        acc[2][0]+=a2*b0; acc[2][1]+=a2*b1; acc[2][2]+=a2*b2; acc[2][3]+=a2*b3;
        acc[3][0]+=a3*b0; acc[3][1]+=a3*b1; acc[3][2]+=a3*b2; acc[3][3]+=a3*b3;
    }
    float* st=g_st+(size_t)(bh*NCH+ch)*4096;
    #pragma unroll
    for(int i=0;i<4;i++) for(int j=0;j<4;j++) st[(ty*4+i)*64+tx*4+j]=acc[i][j];
    if(tid<64){
        float s=0.f;
        #pragma unroll 8
        for(int t=0;t<64;t++) s+=Kp[t*64+tid];
        g_ks[(bh*NCH+ch)*64+tid]=s;
    }
}

// ---------------- K3b: exclusive scan over chunks -----------------
__global__ __launch_bounds__(256) void k_lscan()
{
    const int bh=blockIdx.x, tid=threadIdx.x;
    for(int e=tid;e<4096;e+=256){
        float run=0.f;
        #pragma unroll
        for(int ch=0;ch<NCH;ch++){
            float* p=&g_st[(size_t)(bh*NCH+ch)*4096+e];
            float tv=*p; *p=run; run+=tv;
        }
    }
    if(tid<64){
        float run=0.f;
        #pragma unroll
        for(int ch=0;ch<NCH;ch++){
            float* p=&g_ks[(bh*NCH+ch)*64+tid];
            float tv=*p; *p=run; run+=tv;
        }
    }
}

// ---------------- K3c: linear-attn output -----------------
__global__ __launch_bounds__(256) void k_lout()
{
    __shared__ __align__(16) float bufQ[64*64];
    __shared__ float bufA[64*65];
    __shared__ float ks0[64], den[64];
    const int tid=threadIdx.x, ch=blockIdx.x, bh=blockIdx.y, t0=ch*LCH;
    const int tx=tid&15, ty=tid>>4;
    const float* qb=g_q+(size_t)bh*Tn*Dn;
    const float* kb=g_k+(size_t)bh*Tn*Dn;
    const float* vb=g_v+(size_t)bh*Tn*Dn;
    const float* S0=g_st+(size_t)(bh*NCH+ch)*4096;
    #pragma unroll
    for(int it=0;it<4;it++){
        int f=it*256+tid, t=f>>4, d4=(f&15)<<2;
        float4 q4=*(const float4*)&qb[(size_t)(t0+t)*64+d4];
        float4 qp; qp.x=elup(q4.x*0.125f); qp.y=elup(q4.y*0.125f); qp.z=elup(q4.z*0.125f); qp.w=elup(q4.w*0.125f);
        *(float4*)&bufQ[t*64+d4]=qp;
        float4 k4=*(const float4*)&kb[(size_t)(t0+t)*64+d4];
        bufA[t*65+d4]=elup(k4.x*0.125f); bufA[t*65+d4+1]=elup(k4.y*0.125f);
        bufA[t*65+d4+2]=elup(k4.z*0.125f); bufA[t*65+d4+3]=elup(k4.w*0.125f);
    }
    if(tid<64) ks0[tid]=g_ks[(bh*NCH+ch)*64+tid];
    __syncthreads();
    float A4[4][4], o[4][4];
    #pragma unroll
    for(int i=0;i<4;i++) for(int j=0;j<4;j++){ A4[i][j]=0.f; o[i][j]=0.f; }
    #pragma unroll 4
    for(int d=0;d<64;d++){
        float a0=bufQ[(ty*4+0)*64+d], a1=bufQ[(ty*4+1)*64+d];
        float a2=bufQ[(ty*4+2)*64+d], a3=bufQ[(ty*4+3)*64+d];
        float b0=bufA[(tx*4+0)*65+d], b1=bufA[(tx*4+1)*65+d];
        float b2=bufA[(tx*4+2)*65+d], b3=bufA[(tx*4+3)*65+d];
        A4[0][0]+=a0*b0; A4[0][1]+=a0*b1; A4[0][2]+=a0*b2; A4[0][3]+=a0*b3;
        A4[1][0]+=a1*b0; A4[1][1]+=a1*b1; A4[1][2]+=a1*b2; A4[1][3]+=a1*b3;
        A4[2][0]+=a2*b0; A4[2][1]+=a2*b1; A4[2][2]+=a2*b2; A4[2][3]+=a2*b3;
        A4[3][0]+=a3*b0; A4[3][1]+=a3*b1; A4[3][2]+=a3*b2; A4[3][3]+=a3*b3;
        float4 s4=*(const float4*)&S0[d*64+tx*4];
        o[0][0]+=a0*s4.x; o[0][1]+=a0*s4.y; o[0][2]+=a0*s4.z; o[0][3]+=a0*s4.w;
        o[1][0]+=a1*s4.x; o[1][1]+=a1*s4.y; o[1][2]+=a1*s4.z; o[1][3]+=a1*s4.w;
        o[2][0]+=a2*s4.x; o[2][1]+=a2*s4.y; o[2][2]+=a2*s4.z; o[2][3]+=a2*s4.w;
        o[3][0]+=a3*s4.x; o[3][1]+=a3*s4.y; o[3][2]+=a3*s4.z; o[3][3]+=a3*s4.w;
    }
    __syncthreads();
    #pragma unroll
    for(int i=0;i<4;i++) for(int j=0;j<4;j++){
        int t=ty*4+i, s=tx*4+j;
        bufA[t*65+s] = (s<=t)? A4[i][j] : 0.f;
    }
    __syncthreads();
    if(tid<64){
        float dsum=0.f;
        #pragma unroll 8
        for(int s=0;s<64;s++) dsum+=bufA[tid*65+s];
        #pragma unroll 8
        for(int d=0;d<64;d++) dsum+=bufQ[tid*64+d]*ks0[d];
        den[tid]=dsum;
    }
    #pragma unroll 4
    for(int s=0;s<64;s++){
        float a0=bufA[(ty*4+0)*65+s], a1=bufA[(ty*4+1)*65+s];
        float a2=bufA[(ty*4+2)*65+s], a3=bufA[(ty*4+3)*65+s];
        float4 v4=*(const float4*)&vb[(size_t)(t0+s)*64+tx*4];
        o[0][0]+=a0*v4.x; o[0][1]+=a0*v4.y; o[0][2]+=a0*v4.z; o[0][3]+=a0*v4.w;
        o[1][0]+=a1*v4.x; o[1][1]+=a1*v4.y; o[1][2]+=a1*v4.z; o[1][3]+=a1*v4.w;
        o[2][0]+=a2*v4.x; o[2][1]+=a2*v4.y; o[2][2]+=a2*v4.z; o[2][3]+=a2*v4.w;
        o[3][0]+=a3*v4.x; o[3][1]+=a3*v4.y; o[3][2]+=a3*v4.z; o[3][3]+=a3*v4.w;
    }
    __syncthreads();
    float* yb=g_yl+(size_t)bh*Tn*Dn;
    #pragma unroll
    for(int i=0;i<4;i++){
        float inv=1.f/(den[ty*4+i]+1e-4f);
        #pragma unroll
        for(int j=0;j<4;j++) yb[(size_t)(t0+ty*4+i)*64+tx*4+j]=o[i][j]*inv;
    }
}

// ---------------- K4: epilogue megakernel -----------------
__device__ __forceinline__ void bred2(float& s, float& ss, float* scr, int tid){
    #pragma unroll
    for(int off=16;off>0;off>>=1){
        s += __shfl_xor_sync(0xffffffffu, s, off);
        ss+= __shfl_xor_sync(0xffffffffu, ss, off);
    }
    int w=tid>>5;
    if((tid&31)==0){ scr[w]=s; scr[8+w]=ss; }
    __syncthreads();
    if(tid<8){ s=scr[tid]; ss=scr[8+tid]; }
    else { s=0.f; ss=0.f; }
    if(tid<32){
        #pragma unroll
        for(int off=4;off>0;off>>=1){
            s += __shfl_xor_sync(0xffffffffu, s, off);
            ss+= __shfl_xor_sync(0xffffffffu, ss, off);
        }
        if(tid==0){ scr[16]=s; scr[17]=ss; }
    }
    __syncthreads();
    s=scr[16]; ss=scr[17];
    __syncthreads();
}

__global__ __launch_bounds__(256) void k_epi(
    const float* __restrict__ fg,
    const float* __restrict__ ang, const float* __restrict__ anb,
    const float* __restrict__ ong, const float* __restrict__ onb,
    const float* __restrict__ pg,  const float* __restrict__ pb,
    const float* __restrict__ bw,  const float* __restrict__ wrow,
    const float* __restrict__ wcol,const float* __restrict__ pa_,
    const float* __restrict__ pbias, float* __restrict__ out)
{
    __shared__ float yv[1024];
    __shared__ float xn[1024];
    __shared__ float z[32*33];
    __shared__ float scr[18];
    const int tid=threadIdx.x;
    const int bt=blockIdx.x, b=bt>>10, t=bt&1023;
    const float alpha=1.f/(1.f+__expf(-fg[0]));
    const float pav=pa_[0];
    {
        int h=tid>>4, l=tid&15, d0=l*4;
        size_t base=(((size_t)(b*Hn+h))*Tn+t)*Dn;
        float4 v4=*(const float4*)&g_yl[base+d0];
        float s=v4.x+v4.y+v4.z+v4.w;
        float ss=v4.x*v4.x+v4.y*v4.y+v4.z*v4.z+v4.w*v4.w;
        #pragma unroll
        for(int off=8;off>0;off>>=1){
            s += __shfl_xor_sync(0xffffffffu, s, off, 16);
            ss+= __shfl_xor_sync(0xffffffffu, ss, off, 16);
        }
        float m=s*(1.f/64.f), var=ss*(1.f/64.f)-m*m;
        float rs=rsqrtf(var+1e-5f);
        float4 s4=*(const float4*)&g_ys[base+d0];
        float r[4]={v4.x,v4.y,v4.z,v4.w}, sh[4]={s4.x,s4.y,s4.z,s4.w};
        #pragma unroll
        for(int q=0;q<4;q++){
            float ln=(r[q]-m)*rs*ang[d0+q]+anb[d0+q];
            yv[h*64+d0+q]=alpha*sh[q]+(1.f-alpha)*ln;
        }
    }
    __syncthreads();
    {
        float s=0.f, ss=0.f;
        #pragma unroll
        for(int q=0;q<4;q++){ float v=yv[tid*4+q]; s+=v; ss+=v*v; }
        bred2(s,ss,scr,tid);
        float m=s*(1.f/1024.f), var=ss*(1.f/1024.f)-m*m, rs=rsqrtf(var+1e-5f);
        #pragma unroll
        for(int q=0;q<4;q++){
            int c=tid*4+q;
            yv[c]=(yv[c]-m)*rs*ong[c]+onb[c];
        }
    }
    __syncthreads();
    {
        float s=0.f, ss=0.f;
        #pragma unroll
        for(int q=0;q<4;q++){ float v=yv[tid*4+q]; s+=v; ss+=v*v; }
        bred2(s,ss,scr,tid);
        float m=s*(1.f/1024.f), var=ss*(1.f/1024.f)-m*m, rs=rsqrtf(var+1e-5f);
        #pragma unroll
        for(int q=0;q<4;q++){
            int c=tid*4+q;
            xn[c]=(yv[c]-m)*rs*pg[c]+pb[c];
        }
    }
    __syncthreads();
    #pragma unroll
    for(int q=0;q<4;q++){
        int p=tid*4+q, i=p>>5, c=p&31;
        float acc=0.f;
        #pragma unroll 8
        for(int j=0;j<32;j++) acc+=xn[i*32+j]*wcol[j*32+c];
        z[i*33+c]=acc;
    }
    __syncthreads();
    float* orow=out+(size_t)bt*1024;
    #pragma unroll
    for(int q=0;q<4;q++){
        int p=tid*4+q;
        int mrev=1023-p, gm=mrev>>4, jj=mrev&15;
        float bo=0.f;
        #pragma unroll
        for(int i=0;i<16;i++) bo+=xn[gm*16+i]*bw[(gm*16+i)*16+jj];
        int gi=p>>5, r=p&31;
        float zz=0.f;
        #pragma unroll 8
        for(int c=0;c<32;c++) zz+=z[gi*33+c]*wrow[r*32+c];
        orow[p]=bo+pav*zz+pbias[p];
    }
}

extern "C" void kernel_launch(void* const* d_in, const int* in_sizes, int n_in,
                              void* d_out, int out_size)
{
    const float* x    =(const float*)d_in[0];
    const float* caw  =(const float*)d_in[1];
    const float* cab  =(const float*)d_in[2];
    const float* fg   =(const float*)d_in[3];
    const float* ang  =(const float*)d_in[4];
    const float* anb  =(const float*)d_in[5];
    const float* ong  =(const float*)d_in[6];
    const float* onb  =(const float*)d_in[7];
    const float* ppg  =(const float*)d_in[8];
    const float* ppb  =(const float*)d_in[9];
    const float* pbw  =(const float*)d_in[10];
    const float* pwr  =(const float*)d_in[11];
    const float* pwc  =(const float*)d_in[12];
    const float* pal  =(const float*)d_in[13];
    const float* pbi  =(const float*)d_in[14];
    float* out=(float*)d_out;

    k_qkv<<<dim3(24,16),256>>>(x,caw,cab);
    k_attn<<<dim3(16,32),256>>>();
    k_lchunk<<<dim3(NCH,32),256>>>();
    k_lscan<<<32,256>>>();
    k_lout<<<dim3(NCH,32),256>>>();
    k_epi<<<2048,256>>>(fg,ang,anb,ong,onb,ppg,ppb,pbw,pwr,pwc,pal,pbi,out);
}

// round 8
// speedup vs baseline: 1.8965x; 1.4389x over previous
#include <cuda_runtime.h>
#include <cuda_bf16.h>
#include <math.h>

#define Tn 1024
#define Hn 16
#define Dn 64
#define BHn 32
#define NCH 16
#define LCH 64

__device__ float g_q [BHn*Tn*Dn];
__device__ float g_k [BHn*Tn*Dn];
__device__ float g_v [BHn*Tn*Dn];
__device__ float g_ys[BHn*Tn*Dn];
__device__ float g_yl[BHn*Tn*Dn];
__device__ float g_st[BHn*NCH*Dn*Dn];
__device__ float g_ks[BHn*NCH*Dn];
// bf16 hi/lo split buffers
__device__ __nv_bfloat16 g_xh[2048*1024], g_xl[2048*1024];
__device__ __nv_bfloat16 g_wh[3072*1024], g_wl[3072*1024];
__device__ __nv_bfloat16 g_kh[BHn*Tn*Dn], g_kl[BHn*Tn*Dn];
__device__ __nv_bfloat16 g_vh[BHn*Dn*Tn], g_vl[BHn*Dn*Tn]; // transposed [bh][d][t]

__device__ __forceinline__ float elup(float x){ return x>0.f? x+1.f : __expf(x); }

__device__ __forceinline__ unsigned pk2(__nv_bfloat16 a, __nv_bfloat16 b){
    __nv_bfloat162 t = __halves2bfloat162(a,b);
    return *(unsigned*)&t;
}
__device__ __forceinline__ void split2(float x, float y, unsigned& hi, unsigned& lo){
    __nv_bfloat16 hx=__float2bfloat16(x), hy=__float2bfloat16(y);
    hi=pk2(hx,hy);
    lo=pk2(__float2bfloat16(x-__bfloat162float(hx)), __float2bfloat16(y-__bfloat162float(hy)));
}
__device__ __forceinline__ void mma16816(float* d, const unsigned* a, const unsigned* b){
    asm volatile("mma.sync.aligned.m16n8k16.row.col.f32.bf16.bf16.f32 "
        "{%0,%1,%2,%3}, {%4,%5,%6,%7}, {%8,%9}, {%0,%1,%2,%3};"
        : "+f"(d[0]),"+f"(d[1]),"+f"(d[2]),"+f"(d[3])
        : "r"(a[0]),"r"(a[1]),"r"(a[2]),"r"(a[3]), "r"(b[0]),"r"(b[1]));
}
#define LDU(arr,idx) (*(const unsigned*)&(arr)[idx])

// ---------------- K0a: pre-split x and w into bf16 hi/lo -----------------
__global__ __launch_bounds__(256) void k_cvt1(const float* __restrict__ x,
                                              const float* __restrict__ w)
{
    const int row=blockIdx.x, tid=threadIdx.x;
    const float* src; __nv_bfloat16 *dh, *dl;
    if(row<2048){ src=x+(size_t)row*1024; dh=g_xh+(size_t)row*1024; dl=g_xl+(size_t)row*1024; }
    else { int r2=row-2048; src=w+(size_t)r2*1024; dh=g_wh+(size_t)r2*1024; dl=g_wl+(size_t)r2*1024; }
    int c=tid*4;
    float4 v=*(const float4*)&src[c];
    unsigned h0,l0,h1,l1;
    split2(v.x,v.y,h0,l0); split2(v.z,v.w,h1,l1);
    *(uint2*)&dh[c]=make_uint2(h0,h1);
    *(uint2*)&dl[c]=make_uint2(l0,l1);
}

// ---------------- K0b: pre-split k (row) and v (transposed) -----------------
__global__ __launch_bounds__(256) void k_cvt2()
{
    __shared__ float vsm[64*65];
    const int bh=blockIdx.x, t0=blockIdx.y*64, tid=threadIdx.x;
    const float* kb=g_k+(size_t)bh*Tn*Dn;
    const float* vb=g_v+(size_t)bh*Tn*Dn;
    #pragma unroll
    for(int it=0;it<4;it++){
        int f=it*256+tid, t=f>>4, d4=(f&15)<<2;
        float4 kv=*(const float4*)&kb[(size_t)(t0+t)*64+d4];
        unsigned h0,l0,h1,l1;
        split2(kv.x,kv.y,h0,l0); split2(kv.z,kv.w,h1,l1);
        size_t o=((size_t)bh*Tn+(t0+t))*64+d4;
        *(uint2*)&g_kh[o]=make_uint2(h0,h1);
        *(uint2*)&g_kl[o]=make_uint2(l0,l1);
        float4 vv=*(const float4*)&vb[(size_t)(t0+t)*64+d4];
        vsm[t*65+d4]=vv.x; vsm[t*65+d4+1]=vv.y; vsm[t*65+d4+2]=vv.z; vsm[t*65+d4+3]=vv.w;
    }
    __syncthreads();
    #pragma unroll
    for(int it=0;it<8;it++){
        int idx=it*256+tid, d=idx>>5, tp=idx&31;
        float a=vsm[(2*tp)*65+d], b=vsm[(2*tp+1)*65+d];
        unsigned hi,lo; split2(a,b,hi,lo);
        size_t o=((size_t)bh*64+d)*1024+t0+2*tp;
        *(unsigned*)&g_vh[o]=hi;
        *(unsigned*)&g_vl[o]=lo;
    }
}

// ---------------- K1: QKV GEMM (bf16 split-3, pre-converted inputs) -----------------
#define KT 32
#define LDA 40
__global__ __launch_bounds__(256) void k_qkv(const float* __restrict__ bias)
{
    __shared__ __align__(16) __nv_bfloat16 Ah[128*LDA], Al[128*LDA];
    __shared__ __align__(16) __nv_bfloat16 Bh[128*LDA], Bl[128*LDA];
    const int tid=threadIdx.x;
    const int m0=blockIdx.y*128, n0=blockIdx.x*128;
    const int wid=tid>>5, lane=tid&31;
    const int wm=wid&1, wn=wid>>1;
    const int g=lane>>2, tg=lane&3;

    float acc[4][4][4];
    #pragma unroll
    for(int a=0;a<4;a++) for(int b=0;b<4;b++) for(int c=0;c<4;c++) acc[a][b][c]=0.f;

    for(int k0=0;k0<1024;k0+=KT){
        #pragma unroll
        for(int it=0;it<2;it++){
            int f=it*256+tid, r=f>>2, c=f&3;
            *(uint4*)&Ah[r*LDA+c*8]=*(const uint4*)&g_xh[(size_t)(m0+r)*1024+k0+c*8];
            *(uint4*)&Al[r*LDA+c*8]=*(const uint4*)&g_xl[(size_t)(m0+r)*1024+k0+c*8];
            *(uint4*)&Bh[r*LDA+c*8]=*(const uint4*)&g_wh[(size_t)(n0+r)*1024+k0+c*8];
            *(uint4*)&Bl[r*LDA+c*8]=*(const uint4*)&g_wl[(size_t)(n0+r)*1024+k0+c*8];
        }
        __syncthreads();
        #pragma unroll
        for(int ks=0;ks<KT;ks+=16){
            unsigned ah[4][4], al[4][4], bh[4][2], bl[4][2];
            #pragma unroll
            for(int mi=0;mi<4;mi++){
                int r0=(wm*64+mi*16+g)*LDA + ks + 2*tg;
                int r1=r0 + 8*LDA;
                ah[mi][0]=LDU(Ah,r0); ah[mi][1]=LDU(Ah,r1);
                ah[mi][2]=LDU(Ah,r0+8); ah[mi][3]=LDU(Ah,r1+8);
                al[mi][0]=LDU(Al,r0); al[mi][1]=LDU(Al,r1);
                al[mi][2]=LDU(Al,r0+8); al[mi][3]=LDU(Al,r1+8);
            }
            #pragma unroll
            for(int nj=0;nj<4;nj++){
                int rn=(wn*32+nj*8+g)*LDA + ks + 2*tg;
                bh[nj][0]=LDU(Bh,rn); bh[nj][1]=LDU(Bh,rn+8);
                bl[nj][0]=LDU(Bl,rn); bl[nj][1]=LDU(Bl,rn+8);
            }
            #pragma unroll
            for(int mi=0;mi<4;mi++)
            #pragma unroll
            for(int nj=0;nj<4;nj++){
                mma16816(acc[mi][nj], ah[mi], bh[nj]);
                mma16816(acc[mi][nj], ah[mi], bl[nj]);
                mma16816(acc[mi][nj], al[mi], bh[nj]);
            }
        }
        __syncthreads();
    }
    const int sect=n0>>10;
    float* outp = sect==0? g_q : (sect==1? g_k : g_v);
    const int nc0=n0&1023;
    #pragma unroll
    for(int mi=0;mi<4;mi++){
        int mr=m0+wm*64+mi*16+g;
        #pragma unroll
        for(int half=0;half<2;half++){
            int m=mr+half*8, b=m>>10, t=m&1023;
            #pragma unroll
            for(int nj=0;nj<4;nj++){
                int off=wn*32+nj*8+2*tg;
                int cc=nc0+off, h=cc>>6, d=cc&63;
                int gn=n0+off;
                float2 o2;
                o2.x=acc[mi][nj][half*2+0]+bias[gn];
                o2.y=acc[mi][nj][half*2+1]+bias[gn+1];
                *(float2*)&outp[(((size_t)(b*Hn+h))*Tn+t)*Dn+d]=o2;
            }
        }
    }
}

// ---------------- K2: causal softmax attention (tensor-core flash) -----------------
__global__ __launch_bounds__(128) void k_attn()
{
    __shared__ __align__(16) __nv_bfloat16 Kh[32*72], Kl[32*72];
    __shared__ __align__(16) __nv_bfloat16 Vh[64*40], Vl[64*40];
    const int tid=threadIdx.x, qi=blockIdx.x, bh=blockIdx.y, q0=qi*64;
    const int wid=tid>>5, lane=tid&31, g=lane>>2, tg=lane&3;
    const int row0=q0+wid*16+g, row1=row0+8;
    const float* qb=g_q+(size_t)bh*Tn*Dn;
    const __nv_bfloat16* khb=g_kh+(size_t)bh*Tn*Dn;
    const __nv_bfloat16* klb=g_kl+(size_t)bh*Tn*Dn;
    const __nv_bfloat16* vhb=g_vh+(size_t)bh*Dn*Tn;
    const __nv_bfloat16* vlb=g_vl+(size_t)bh*Dn*Tn;

    unsigned qh[4][4], ql[4][4];
    #pragma unroll
    for(int ks=0;ks<4;ks++){
        float2 p00=*(const float2*)&qb[(size_t)row0*64+ks*16+2*tg];
        float2 p10=*(const float2*)&qb[(size_t)row1*64+ks*16+2*tg];
        float2 p01=*(const float2*)&qb[(size_t)row0*64+ks*16+8+2*tg];
        float2 p11=*(const float2*)&qb[(size_t)row1*64+ks*16+8+2*tg];
        split2(p00.x,p00.y,qh[ks][0],ql[ks][0]);
        split2(p10.x,p10.y,qh[ks][1],ql[ks][1]);
        split2(p01.x,p01.y,qh[ks][2],ql[ks][2]);
        split2(p11.x,p11.y,qh[ks][3],ql[ks][3]);
    }

    float o[8][4];
    #pragma unroll
    for(int i=0;i<8;i++) for(int j=0;j<4;j++) o[i][j]=0.f;
    float m0=-1e30f, m1=-1e30f, l0=0.f, l1=0.f;

    const int nkt=2*qi+2;
    for(int kt=0;kt<nkt;kt++){
        const int k0=kt*32;
        __syncthreads();
        #pragma unroll
        for(int it=0;it<2;it++){
            int f=it*128+tid;
            int r=f>>3, c=f&7;
            *(uint4*)&Kh[r*72+c*8]=*(const uint4*)&khb[(size_t)(k0+r)*64+c*8];
            *(uint4*)&Kl[r*72+c*8]=*(const uint4*)&klb[(size_t)(k0+r)*64+c*8];
            int d=f>>2, c2=f&3;
            *(uint4*)&Vh[d*40+c2*8]=*(const uint4*)&vhb[(size_t)d*1024+k0+c2*8];
            *(uint4*)&Vl[d*40+c2*8]=*(const uint4*)&vlb[(size_t)d*1024+k0+c2*8];
        }
        __syncthreads();

        float sa[4][4];
        #pragma unroll
        for(int nt=0;nt<4;nt++) for(int j=0;j<4;j++) sa[nt][j]=0.f;
        #pragma unroll
        for(int ks=0;ks<4;ks++){
            #pragma unroll
            for(int nt=0;nt<4;nt++){
                int base=(nt*8+g)*72+ks*16+2*tg;
                unsigned bhf[2]={LDU(Kh,base),LDU(Kh,base+8)};
                unsigned blf[2]={LDU(Kl,base),LDU(Kl,base+8)};
                mma16816(sa[nt], qh[ks], bhf);
                mma16816(sa[nt], qh[ks], blf);
                mma16816(sa[nt], ql[ks], bhf);
            }
        }
        float ps[4][4];
        float mx0=-1e30f, mx1=-1e30f;
        #pragma unroll
        for(int nt=0;nt<4;nt++){
            int c0=k0+nt*8+2*tg, c1=c0+1;
            float s0=sa[nt][0]*0.125f; if(c0>row0) s0=-1e30f;
            float s1=sa[nt][1]*0.125f; if(c1>row0) s1=-1e30f;
            float s2=sa[nt][2]*0.125f; if(c0>row1) s2=-1e30f;
            float s3=sa[nt][3]*0.125f; if(c1>row1) s3=-1e30f;
            ps[nt][0]=s0; ps[nt][1]=s1; ps[nt][2]=s2; ps[nt][3]=s3;
            mx0=fmaxf(mx0,fmaxf(s0,s1)); mx1=fmaxf(mx1,fmaxf(s2,s3));
        }
        mx0=fmaxf(mx0,__shfl_xor_sync(0xffffffffu,mx0,1));
        mx0=fmaxf(mx0,__shfl_xor_sync(0xffffffffu,mx0,2));
        mx1=fmaxf(mx1,__shfl_xor_sync(0xffffffffu,mx1,1));
        mx1=fmaxf(mx1,__shfl_xor_sync(0xffffffffu,mx1,2));
        float mn0=fmaxf(m0,mx0), mn1=fmaxf(m1,mx1);
        float cr0=__expf(m0-mn0), cr1=__expf(m1-mn1);
        m0=mn0; m1=mn1;
        float sum0=0.f, sum1=0.f;
        #pragma unroll
        for(int nt=0;nt<4;nt++){
            ps[nt][0]=__expf(ps[nt][0]-mn0); ps[nt][1]=__expf(ps[nt][1]-mn0);
            ps[nt][2]=__expf(ps[nt][2]-mn1); ps[nt][3]=__expf(ps[nt][3]-mn1);
            sum0+=ps[nt][0]+ps[nt][1]; sum1+=ps[nt][2]+ps[nt][3];
        }
        sum0+=__shfl_xor_sync(0xffffffffu,sum0,1);
        sum0+=__shfl_xor_sync(0xffffffffu,sum0,2);
        sum1+=__shfl_xor_sync(0xffffffffu,sum1,1);
        sum1+=__shfl_xor_sync(0xffffffffu,sum1,2);
        l0=l0*cr0+sum0; l1=l1*cr1+sum1;
        #pragma unroll
        for(int ntv=0;ntv<8;ntv++){
            o[ntv][0]*=cr0; o[ntv][1]*=cr0; o[ntv][2]*=cr1; o[ntv][3]*=cr1;
        }
        #pragma unroll
        for(int ks2=0;ks2<2;ks2++){
            unsigned ah[4], al[4];
            split2(ps[2*ks2][0],  ps[2*ks2][1],  ah[0], al[0]);
            split2(ps[2*ks2][2],  ps[2*ks2][3],  ah[1], al[1]);
            split2(ps[2*ks2+1][0],ps[2*ks2+1][1],ah[2], al[2]);
            split2(ps[2*ks2+1][2],ps[2*ks2+1][3],ah[3], al[3]);
            #pragma unroll
            for(int ntv=0;ntv<8;ntv++){
                int base=(ntv*8+g)*40+ks2*16+2*tg;
                unsigned bhf[2]={LDU(Vh,base),LDU(Vh,base+8)};
                unsigned blf[2]={LDU(Vl,base),LDU(Vl,base+8)};
                mma16816(o[ntv], ah, bhf);
                mma16816(o[ntv], ah, blf);
                mma16816(o[ntv], al, bhf);
            }
        }
    }
    float i0=1.f/l0, i1=1.f/l1;
    float* yb=g_ys+(size_t)bh*Tn*Dn;
    #pragma unroll
    for(int ntv=0;ntv<8;ntv++){
        float2 w0; w0.x=o[ntv][0]*i0; w0.y=o[ntv][1]*i0;
        float2 w1; w1.x=o[ntv][2]*i1; w1.y=o[ntv][3]*i1;
        *(float2*)&yb[(size_t)row0*64+ntv*8+2*tg]=w0;
        *(float2*)&yb[(size_t)row1*64+ntv*8+2*tg]=w1;
    }
}

// ---------------- K3a: linear-attn chunk sums -----------------
__global__ __launch_bounds__(256) void k_lchunk()
{
    __shared__ __align__(16) float Kp[64*64];
    __shared__ __align__(16) float vv[64*64];
    const int tid=threadIdx.x, ch=blockIdx.x, bh=blockIdx.y, t0=ch*LCH;
    const float* kb=g_k+(size_t)bh*Tn*Dn;
    const float* vb=g_v+(size_t)bh*Tn*Dn;
    #pragma unroll
    for(int it=0;it<4;it++){
        int f=it*256+tid, t=f>>4, d4=(f&15)<<2;
        float4 k4=*(const float4*)&kb[(size_t)(t0+t)*64+d4];
        float4 kp; kp.x=elup(k4.x*0.125f); kp.y=elup(k4.y*0.125f); kp.z=elup(k4.z*0.125f); kp.w=elup(k4.w*0.125f);
        *(float4*)&Kp[t*64+d4]=kp;
        *(float4*)&vv[t*64+d4]=*(const float4*)&vb[(size_t)(t0+t)*64+d4];
    }
    __syncthreads();
    const int tx=tid&15, ty=tid>>4;
    float acc[4][4];
    #pragma unroll
    for(int i=0;i<4;i++) for(int j=0;j<4;j++) acc[i][j]=0.f;
    #pragma unroll 8
    for(int t=0;t<64;t++){
        float a0=Kp[t*64+ty*4], a1=Kp[t*64+ty*4+1], a2=Kp[t*64+ty*4+2], a3=Kp[t*64+ty*4+3];
        float b0=vv[t*64+tx*4], b1=vv[t*64+tx*4+1], b2=vv[t*64+tx*4+2], b3=vv[t*64+tx*4+3];
        acc[0][0]+=a0*b0; acc[0][1]+=a0*b1; acc[0][2]+=a0*b2; acc[0][3]+=a0*b3;
        acc[1][0]+=a1*b0; acc[1][1]+=a1*b1; acc[1][2]+=a1*b2; acc[1][3]+=a1*b3;
        acc[2][0]+=a2*b0; acc[2][1]+=a2*b1; acc[2][2]+=a2*b2; acc[2][3]+=a2*b3;
        acc[3][0]+=a3*b0; acc[3][1]+=a3*b1; acc[3][2]+=a3*b2; acc[3][3]+=a3*b3;
    }
    float* st=g_st+(size_t)(bh*NCH+ch)*4096;
    #pragma unroll
    for(int i=0;i<4;i++) for(int j=0;j<4;j++) st[(ty*4+i)*64+tx*4+j]=acc[i][j];
    if(tid<64){
        float s=0.f;
        #pragma unroll 8
        for(int t=0;t<64;t++) s+=Kp[t*64+tid];
        g_ks[(bh*NCH+ch)*64+tid]=s;
    }
}

// ---------------- K3b: exclusive scan over chunks -----------------
__global__ __launch_bounds__(256) void k_lscan()
{
    const int bh=blockIdx.x, tid=threadIdx.x;
    for(int e=tid;e<4096;e+=256){
        float run=0.f;
        #pragma unroll
        for(int ch=0;ch<NCH;ch++){
            float* p=&g_st[(size_t)(bh*NCH+ch)*4096+e];
            float tv=*p; *p=run; run+=tv;
        }
    }
    if(tid<64){
        float run=0.f;
        #pragma unroll
        for(int ch=0;ch<NCH;ch++){
            float* p=&g_ks[(bh*NCH+ch)*64+tid];
            float tv=*p; *p=run; run+=tv;
        }
    }
}

// ---------------- K3c: linear-attn output -----------------
__global__ __launch_bounds__(256) void k_lout()
{
    __shared__ __align__(16) float bufQ[64*64];
    __shared__ float bufA[64*65];
    __shared__ float ks0[64], den[64];
    const int tid=threadIdx.x, ch=blockIdx.x, bh=blockIdx.y, t0=ch*LCH;
    const int tx=tid&15, ty=tid>>4;
    const float* qb=g_q+(size_t)bh*Tn*Dn;
    const float* kb=g_k+(size_t)bh*Tn*Dn;
    const float* vb=g_v+(size_t)bh*Tn*Dn;
    const float* S0=g_st+(size_t)(bh*NCH+ch)*4096;
    #pragma unroll
    for(int it=0;it<4;it++){
        int f=it*256+tid, t=f>>4, d4=(f&15)<<2;
        float4 q4=*(const float4*)&qb[(size_t)(t0+t)*64+d4];
        float4 qp; qp.x=elup(q4.x*0.125f); qp.y=elup(q4.y*0.125f); qp.z=elup(q4.z*0.125f); qp.w=elup(q4.w*0.125f);
        *(float4*)&bufQ[t*64+d4]=qp;
        float4 k4=*(const float4*)&kb[(size_t)(t0+t)*64+d4];
        bufA[t*65+d4]=elup(k4.x*0.125f); bufA[t*65+d4+1]=elup(k4.y*0.125f);
        bufA[t*65+d4+2]=elup(k4.z*0.125f); bufA[t*65+d4+3]=elup(k4.w*0.125f);
    }
    if(tid<64) ks0[tid]=g_ks[(bh*NCH+ch)*64+tid];
    __syncthreads();
    float A4[4][4], o[4][4];
    #pragma unroll
    for(int i=0;i<4;i++) for(int j=0;j<4;j++){ A4[i][j]=0.f; o[i][j]=0.f; }
    #pragma unroll 4
    for(int d=0;d<64;d++){
        float a0=bufQ[(ty*4+0)*64+d], a1=bufQ[(ty*4+1)*64+d];
        float a2=bufQ[(ty*4+2)*64+d], a3=bufQ[(ty*4+3)*64+d];
        float b0=bufA[(tx*4+0)*65+d], b1=bufA[(tx*4+1)*65+d];
        float b2=bufA[(tx*4+2)*65+d], b3=bufA[(tx*4+3)*65+d];
        A4[0][0]+=a0*b0; A4[0][1]+=a0*b1; A4[0][2]+=a0*b2; A4[0][3]+=a0*b3;
        A4[1][0]+=a1*b0; A4[1][1]+=a1*b1; A4[1][2]+=a1*b2; A4[1][3]+=a1*b3;
        A4[2][0]+=a2*b0; A4[2][1]+=a2*b1; A4[2][2]+=a2*b2; A4[2][3]+=a2*b3;
        A4[3][0]+=a3*b0; A4[3][1]+=a3*b1; A4[3][2]+=a3*b2; A4[3][3]+=a3*b3;
        float4 s4=*(const float4*)&S0[d*64+tx*4];
        o[0][0]+=a0*s4.x; o[0][1]+=a0*s4.y; o[0][2]+=a0*s4.z; o[0][3]+=a0*s4.w;
        o[1][0]+=a1*s4.x; o[1][1]+=a1*s4.y; o[1][2]+=a1*s4.z; o[1][3]+=a1*s4.w;
        o[2][0]+=a2*s4.x; o[2][1]+=a2*s4.y; o[2][2]+=a2*s4.z; o[2][3]+=a2*s4.w;
        o[3][0]+=a3*s4.x; o[3][1]+=a3*s4.y; o[3][2]+=a3*s4.z; o[3][3]+=a3*s4.w;
    }
    __syncthreads();
    #pragma unroll
    for(int i=0;i<4;i++) for(int j=0;j<4;j++){
        int t=ty*4+i, s=tx*4+j;
        bufA[t*65+s] = (s<=t)? A4[i][j] : 0.f;
    }
    __syncthreads();
    if(tid<64){
        float dsum=0.f;
        #pragma unroll 8
        for(int s=0;s<64;s++) dsum+=bufA[tid*65+s];
        #pragma unroll 8
        for(int d=0;d<64;d++) dsum+=bufQ[tid*64+d]*ks0[d];
        den[tid]=dsum;
    }
    #pragma unroll 4
    for(int s=0;s<64;s++){
        float a0=bufA[(ty*4+0)*65+s], a1=bufA[(ty*4+1)*65+s];
        float a2=bufA[(ty*4+2)*65+s], a3=bufA[(ty*4+3)*65+s];
        float4 v4=*(const float4*)&vb[(size_t)(t0+s)*64+tx*4];
        o[0][0]+=a0*v4.x; o[0][1]+=a0*v4.y; o[0][2]+=a0*v4.z; o[0][3]+=a0*v4.w;
        o[1][0]+=a1*v4.x; o[1][1]+=a1*v4.y; o[1][2]+=a1*v4.z; o[1][3]+=a1*v4.w;
        o[2][0]+=a2*v4.x; o[2][1]+=a2*v4.y; o[2][2]+=a2*v4.z; o[2][3]+=a2*v4.w;
        o[3][0]+=a3*v4.x; o[3][1]+=a3*v4.y; o[3][2]+=a3*v4.z; o[3][3]+=a3*v4.w;
    }
    __syncthreads();
    float* yb=g_yl+(size_t)bh*Tn*Dn;
    #pragma unroll
    for(int i=0;i<4;i++){
        float inv=1.f/(den[ty*4+i]+1e-4f);
        #pragma unroll
        for(int j=0;j<4;j++) yb[(size_t)(t0+ty*4+i)*64+tx*4+j]=o[i][j]*inv;
    }
}

// ---------------- K4: epilogue megakernel -----------------
__device__ __forceinline__ void bred2(float& s, float& ss, float* scr, int tid){
    #pragma unroll
    for(int off=16;off>0;off>>=1){
        s += __shfl_xor_sync(0xffffffffu, s, off);
        ss+= __shfl_xor_sync(0xffffffffu, ss, off);
    }
    int w=tid>>5;
    if((tid&31)==0){ scr[w]=s; scr[8+w]=ss; }
    __syncthreads();
    if(tid<8){ s=scr[tid]; ss=scr[8+tid]; }
    else { s=0.f; ss=0.f; }
    if(tid<32){
        #pragma unroll
        for(int off=4;off>0;off>>=1){
            s += __shfl_xor_sync(0xffffffffu, s, off);
            ss+= __shfl_xor_sync(0xffffffffu, ss, off);
        }
        if(tid==0){ scr[16]=s; scr[17]=ss; }
    }
    __syncthreads();
    s=scr[16]; ss=scr[17];
    __syncthreads();
}

__global__ __launch_bounds__(256) void k_epi(
    const float* __restrict__ fg,
    const float* __restrict__ ang, const float* __restrict__ anb,
    const float* __restrict__ ong, const float* __restrict__ onb,
    const float* __restrict__ pg,  const float* __restrict__ pb,
    const float* __restrict__ bw,  const float* __restrict__ wrow,
    const float* __restrict__ wcol,const float* __restrict__ pa_,
    const float* __restrict__ pbias, float* __restrict__ out)
{
    __shared__ float yv[1024];
    __shared__ float xn[1024];
    __shared__ float z[32*33];
    __shared__ float scr[18];
    const int tid=threadIdx.x;
    const int bt=blockIdx.x, b=bt>>10, t=bt&1023;
    const float alpha=1.f/(1.f+__expf(-fg[0]));
    const float pav=pa_[0];
    {
        int h=tid>>4, l=tid&15, d0=l*4;
        size_t base=(((size_t)(b*Hn+h))*Tn+t)*Dn;
        float4 v4=*(const float4*)&g_yl[base+d0];
        float s=v4.x+v4.y+v4.z+v4.w;
        float ss=v4.x*v4.x+v4.y*v4.y+v4.z*v4.z+v4.w*v4.w;
        #pragma unroll
        for(int off=8;off>0;off>>=1){
            s += __shfl_xor_sync(0xffffffffu, s, off, 16);
            ss+= __shfl_xor_sync(0xffffffffu, ss, off, 16);
        }
        float m=s*(1.f/64.f), var=ss*(1.f/64.f)-m*m;
        float rs=rsqrtf(var+1e-5f);
        float4 s4=*(const float4*)&g_ys[base+d0];
        float r[4]={v4.x,v4.y,v4.z,v4.w}, sh[4]={s4.x,s4.y,s4.z,s4.w};
        #pragma unroll
        for(int q=0;q<4;q++){
            float ln=(r[q]-m)*rs*ang[d0+q]+anb[d0+q];
            yv[h*64+d0+q]=alpha*sh[q]+(1.f-alpha)*ln;
        }
    }
    __syncthreads();
    {
        float s=0.f, ss=0.f;
        #pragma unroll
        for(int q=0;q<4;q++){ float v=yv[tid*4+q]; s+=v; ss+=v*v; }
        bred2(s,ss,scr,tid);
        float m=s*(1.f/1024.f), var=ss*(1.f/1024.f)-m*m, rs=rsqrtf(var+1e-5f);
        #pragma unroll
        for(int q=0;q<4;q++){
            int c=tid*4+q;
            yv[c]=(yv[c]-m)*rs*ong[c]+onb[c];
        }
    }
    __syncthreads();
    {
        float s=0.f, ss=0.f;
        #pragma unroll
        for(int q=0;q<4;q++){ float v=yv[tid*4+q]; s+=v; ss+=v*v; }
        bred2(s,ss,scr,tid);
        float m=s*(1.f/1024.f), var=ss*(1.f/1024.f)-m*m, rs=rsqrtf(var+1e-5f);
        #pragma unroll
        for(int q=0;q<4;q++){
            int c=tid*4+q;
            xn[c]=(yv[c]-m)*rs*pg[c]+pb[c];
        }
    }
    __syncthreads();
    #pragma unroll
    for(int q=0;q<4;q++){
        int p=tid*4+q, i=p>>5, c=p&31;
        float acc=0.f;
        #pragma unroll 8
        for(int j=0;j<32;j++) acc+=xn[i*32+j]*wcol[j*32+c];
        z[i*33+c]=acc;
    }
    __syncthreads();
    float* orow=out+(size_t)bt*1024;
    #pragma unroll
    for(int q=0;q<4;q++){
        int p=tid*4+q;
        int mrev=1023-p, gm=mrev>>4, jj=mrev&15;
        float bo=0.f;
        #pragma unroll
        for(int i=0;i<16;i++) bo+=xn[gm*16+i]*bw[(gm*16+i)*16+jj];
        int gi=p>>5, r=p&31;
        float zz=0.f;
        #pragma unroll 8
        for(int c=0;c<32;c++) zz+=z[gi*33+c]*wrow[r*32+c];
        orow[p]=bo+pav*zz+pbias[p];
    }
}

extern "C" void kernel_launch(void* const* d_in, const int* in_sizes, int n_in,
                              void* d_out, int out_size)
{
    const float* x    =(const float*)d_in[0];
    const float* caw  =(const float*)d_in[1];
    const float* cab  =(const float*)d_in[2];
    const float* fg   =(const float*)d_in[3];
    const float* ang  =(const float*)d_in[4];
    const float* anb  =(const float*)d_in[5];
    const float* ong  =(const float*)d_in[6];
    const float* onb  =(const float*)d_in[7];
    const float* ppg  =(const float*)d_in[8];
    const float* ppb  =(const float*)d_in[9];
    const float* pbw  =(const float*)d_in[10];
    const float* pwr  =(const float*)d_in[11];
    const float* pwc  =(const float*)d_in[12];
    const float* pal  =(const float*)d_in[13];
    const float* pbi  =(const float*)d_in[14];
    float* out=(float*)d_out;

    k_cvt1<<<5120,256>>>(x,caw);
    k_qkv<<<dim3(24,16),256>>>(cab);
    k_cvt2<<<dim3(32,16),256>>>();
    k_attn<<<dim3(16,32),128>>>();
    k_lchunk<<<dim3(NCH,32),256>>>();
    k_lscan<<<32,256>>>();
    k_lout<<<dim3(NCH,32),256>>>();
    k_epi<<<2048,256>>>(fg,ang,anb,ong,onb,ppg,ppb,pbw,pwr,pwc,pal,pbi,out);
}

// round 12
// speedup vs baseline: 1.9610x; 1.0340x over previous
#include <cuda_runtime.h>
#include <cuda_bf16.h>
#include <math.h>

#define Tn 1024
#define Hn 16
#define Dn 64
#define BHn 32
#define NCH 16
#define LCH 64

__device__ float g_q [BHn*Tn*Dn];
__device__ float g_k [BHn*Tn*Dn];
__device__ float g_v [BHn*Tn*Dn];
__device__ float g_ys[BHn*Tn*Dn];
__device__ float g_yl[BHn*Tn*Dn];
__device__ float g_st[BHn*NCH*Dn*Dn];
__device__ float g_ks[BHn*NCH*Dn];
__device__ __nv_bfloat16 g_xh[2048*1024], g_xl[2048*1024];
__device__ __nv_bfloat16 g_wh[3072*1024], g_wl[3072*1024];
__device__ __nv_bfloat16 g_kh[BHn*Tn*Dn], g_kl[BHn*Tn*Dn];
__device__ __nv_bfloat16 g_vh[BHn*Dn*Tn], g_vl[BHn*Dn*Tn];

__device__ __forceinline__ float elup(float x){ return x>0.f? x+1.f : __expf(x); }

__device__ __forceinline__ unsigned pk2(__nv_bfloat16 a, __nv_bfloat16 b){
    __nv_bfloat162 t = __halves2bfloat162(a,b);
    return *(unsigned*)&t;
}
__device__ __forceinline__ void split2(float x, float y, unsigned& hi, unsigned& lo){
    __nv_bfloat16 hx=__float2bfloat16(x), hy=__float2bfloat16(y);
    hi=pk2(hx,hy);
    lo=pk2(__float2bfloat16(x-__bfloat162float(hx)), __float2bfloat16(y-__bfloat162float(hy)));
}
__device__ __forceinline__ void mma16816(float* d, const unsigned* a, const unsigned* b){
    asm volatile("mma.sync.aligned.m16n8k16.row.col.f32.bf16.bf16.f32 "
        "{%0,%1,%2,%3}, {%4,%5,%6,%7}, {%8,%9}, {%0,%1,%2,%3};"
        : "+f"(d[0]),"+f"(d[1]),"+f"(d[2]),"+f"(d[3])
        : "r"(a[0]),"r"(a[1]),"r"(a[2]),"r"(a[3]), "r"(b[0]),"r"(b[1]));
}
#define LDU(arr,idx) (*(const unsigned*)&(arr)[idx])

// ---------------- K0a: pre-split x and w into bf16 hi/lo -----------------
__global__ __launch_bounds__(256) void k_cvt1(const float* __restrict__ x,
                                              const float* __restrict__ w)
{
    const int row=blockIdx.x, tid=threadIdx.x;
    const float* src; __nv_bfloat16 *dh, *dl;
    if(row<2048){ src=x+(size_t)row*1024; dh=g_xh+(size_t)row*1024; dl=g_xl+(size_t)row*1024; }
    else { int r2=row-2048; src=w+(size_t)r2*1024; dh=g_wh+(size_t)r2*1024; dl=g_wl+(size_t)r2*1024; }
    int c=tid*4;
    float4 v=*(const float4*)&src[c];
    unsigned h0,l0,h1,l1;
    split2(v.x,v.y,h0,l0); split2(v.z,v.w,h1,l1);
    *(uint2*)&dh[c]=make_uint2(h0,h1);
    *(uint2*)&dl[c]=make_uint2(l0,l1);
}

// ---------------- K0b: pre-split k (row) and v (transposed) -----------------
__global__ __launch_bounds__(256) void k_cvt2()
{
    __shared__ float vsm[64*65];
    const int bh=blockIdx.x, t0=blockIdx.y*64, tid=threadIdx.x;
    const float* kb=g_k+(size_t)bh*Tn*Dn;
    const float* vb=g_v+(size_t)bh*Tn*Dn;
    #pragma unroll
    for(int it=0;it<4;it++){
        int f=it*256+tid, t=f>>4, d4=(f&15)<<2;
        float4 kv=*(const float4*)&kb[(size_t)(t0+t)*64+d4];
        unsigned h0,l0,h1,l1;
        split2(kv.x,kv.y,h0,l0); split2(kv.z,kv.w,h1,l1);
        size_t o=((size_t)bh*Tn+(t0+t))*64+d4;
        *(uint2*)&g_kh[o]=make_uint2(h0,h1);
        *(uint2*)&g_kl[o]=make_uint2(l0,l1);
        float4 vv=*(const float4*)&vb[(size_t)(t0+t)*64+d4];
        vsm[t*65+d4]=vv.x; vsm[t*65+d4+1]=vv.y; vsm[t*65+d4+2]=vv.z; vsm[t*65+d4+3]=vv.w;
    }
    __syncthreads();
    #pragma unroll
    for(int it=0;it<8;it++){
        int idx=it*256+tid, d=idx>>5, tp=idx&31;
        float a=vsm[(2*tp)*65+d], b=vsm[(2*tp+1)*65+d];
        unsigned hi,lo; split2(a,b,hi,lo);
        size_t o=((size_t)bh*64+d)*1024+t0+2*tp;
        *(unsigned*)&g_vh[o]=hi;
        *(unsigned*)&g_vl[o]=lo;
    }
}

// ---------------- K1: QKV GEMM (bf16 split-3, pre-converted inputs) -----------------
#define KT 32
#define LDA 40
__global__ __launch_bounds__(256) void k_qkv(const float* __restrict__ bias)
{
    __shared__ __align__(16) __nv_bfloat16 Ah[128*LDA], Al[128*LDA];
    __shared__ __align__(16) __nv_bfloat16 Bh[128*LDA], Bl[128*LDA];
    const int tid=threadIdx.x;
    const int m0=blockIdx.y*128, n0=blockIdx.x*128;
    const int wid=tid>>5, lane=tid&31;
    const int wm=wid&1, wn=wid>>1;
    const int g=lane>>2, tg=lane&3;

    float acc[4][4][4];
    #pragma unroll
    for(int a=0;a<4;a++) for(int b=0;b<4;b++) for(int c=0;c<4;c++) acc[a][b][c]=0.f;

    for(int k0=0;k0<1024;k0+=KT){
        #pragma unroll
        for(int it=0;it<2;it++){
            int f=it*256+tid, r=f>>2, c=f&3;
            *(uint4*)&Ah[r*LDA+c*8]=*(const uint4*)&g_xh[(size_t)(m0+r)*1024+k0+c*8];
            *(uint4*)&Al[r*LDA+c*8]=*(const uint4*)&g_xl[(size_t)(m0+r)*1024+k0+c*8];
            *(uint4*)&Bh[r*LDA+c*8]=*(const uint4*)&g_wh[(size_t)(n0+r)*1024+k0+c*8];
            *(uint4*)&Bl[r*LDA+c*8]=*(const uint4*)&g_wl[(size_t)(n0+r)*1024+k0+c*8];
        }
        __syncthreads();
        #pragma unroll
        for(int ks=0;ks<KT;ks+=16){
            unsigned ah[4][4], al[4][4], bh[4][2], bl[4][2];
            #pragma unroll
            for(int mi=0;mi<4;mi++){
                int r0=(wm*64+mi*16+g)*LDA + ks + 2*tg;
                int r1=r0 + 8*LDA;
                ah[mi][0]=LDU(Ah,r0); ah[mi][1]=LDU(Ah,r1);
                ah[mi][2]=LDU(Ah,r0+8); ah[mi][3]=LDU(Ah,r1+8);
                al[mi][0]=LDU(Al,r0); al[mi][1]=LDU(Al,r1);
                al[mi][2]=LDU(Al,r0+8); al[mi][3]=LDU(Al,r1+8);
            }
            #pragma unroll
            for(int nj=0;nj<4;nj++){
                int rn=(wn*32+nj*8+g)*LDA + ks + 2*tg;
                bh[nj][0]=LDU(Bh,rn); bh[nj][1]=LDU(Bh,rn+8);
                bl[nj][0]=LDU(Bl,rn); bl[nj][1]=LDU(Bl,rn+8);
            }
            #pragma unroll
            for(int mi=0;mi<4;mi++)
            #pragma unroll
            for(int nj=0;nj<4;nj++){
                mma16816(acc[mi][nj], ah[mi], bh[nj]);
                mma16816(acc[mi][nj], ah[mi], bl[nj]);
                mma16816(acc[mi][nj], al[mi], bh[nj]);
            }
        }
        __syncthreads();
    }
    const int sect=n0>>10;
    float* outp = sect==0? g_q : (sect==1? g_k : g_v);
    const int nc0=n0&1023;
    #pragma unroll
    for(int mi=0;mi<4;mi++){
        int mr=m0+wm*64+mi*16+g;
        #pragma unroll
        for(int half=0;half<2;half++){
            int m=mr+half*8, b=m>>10, t=m&1023;
            #pragma unroll
            for(int nj=0;nj<4;nj++){
                int off=wn*32+nj*8+2*tg;
                int cc=nc0+off, h=cc>>6, d=cc&63;
                int gn=n0+off;
                float2 o2;
                o2.x=acc[mi][nj][half*2+0]+bias[gn];
                o2.y=acc[mi][nj][half*2+1]+bias[gn+1];
                *(float2*)&outp[(((size_t)(b*Hn+h))*Tn+t)*Dn+d]=o2;
            }
        }
    }
}

// ---------------- K2: causal softmax attention (paired tiles, balanced) ---------
// block x handles q-tiles x (half 0) and 15-x (half 1): 34 key tiles total each.
__global__ __launch_bounds__(256) void k_attn()
{
    __shared__ __align__(16) __nv_bfloat16 Kh[2][32*72], Kl[2][32*72];
    __shared__ __align__(16) __nv_bfloat16 Vh[2][64*40], Vl[2][64*40];
    const int tid=threadIdx.x, bh=blockIdx.y;
    const int half=tid>>7, ltid=tid&127;
    const int qi = half? (15-(int)blockIdx.x) : (int)blockIdx.x;
    const int q0=qi*64;
    const int wid=ltid>>5, lane=ltid&31, g=lane>>2, tg=lane&3;
    const int row0=q0+wid*16+g, row1=row0+8;
    const float* qb=g_q+(size_t)bh*Tn*Dn;
    const __nv_bfloat16* khb=g_kh+(size_t)bh*Tn*Dn;
    const __nv_bfloat16* klb=g_kl+(size_t)bh*Tn*Dn;
    const __nv_bfloat16* vhb=g_vh+(size_t)bh*Dn*Tn;
    const __nv_bfloat16* vlb=g_vl+(size_t)bh*Dn*Tn;
    __nv_bfloat16* KhS=Kh[half]; __nv_bfloat16* KlS=Kl[half];
    __nv_bfloat16* VhS=Vh[half]; __nv_bfloat16* VlS=Vl[half];

    unsigned qh[4][4], ql[4][4];
    #pragma unroll
    for(int ks=0;ks<4;ks++){
        float2 p00=*(const float2*)&qb[(size_t)row0*64+ks*16+2*tg];
        float2 p10=*(const float2*)&qb[(size_t)row1*64+ks*16+2*tg];
        float2 p01=*(const float2*)&qb[(size_t)row0*64+ks*16+8+2*tg];
        float2 p11=*(const float2*)&qb[(size_t)row1*64+ks*16+8+2*tg];
        split2(p00.x,p00.y,qh[ks][0],ql[ks][0]);
        split2(p10.x,p10.y,qh[ks][1],ql[ks][1]);
        split2(p01.x,p01.y,qh[ks][2],ql[ks][2]);
        split2(p11.x,p11.y,qh[ks][3],ql[ks][3]);
    }

    float o[8][4];
    #pragma unroll
    for(int i=0;i<8;i++) for(int j=0;j<4;j++) o[i][j]=0.f;
    float m0=-1e30f, m1=-1e30f, l0=0.f, l1=0.f;

    const int nkt=2*qi+2;
    for(int kt=0;kt<nkt;kt++){
        const int k0=kt*32;
        asm volatile("bar.sync %0, 128;" :: "r"(half+1) : "memory");
        #pragma unroll
        for(int it=0;it<2;it++){
            int f=it*128+ltid;
            int r=f>>3, c=f&7;
            *(uint4*)&KhS[r*72+c*8]=*(const uint4*)&khb[(size_t)(k0+r)*64+c*8];
            *(uint4*)&KlS[r*72+c*8]=*(const uint4*)&klb[(size_t)(k0+r)*64+c*8];
            int d=f>>2, c2=f&3;
            *(uint4*)&VhS[d*40+c2*8]=*(const uint4*)&vhb[(size_t)d*1024+k0+c2*8];
            *(uint4*)&VlS[d*40+c2*8]=*(const uint4*)&vlb[(size_t)d*1024+k0+c2*8];
        }
        asm volatile("bar.sync %0, 128;" :: "r"(half+1) : "memory");

        float sa[4][4];
        #pragma unroll
        for(int nt=0;nt<4;nt++) for(int j=0;j<4;j++) sa[nt][j]=0.f;
        #pragma unroll
        for(int ks=0;ks<4;ks++){
            #pragma unroll
            for(int nt=0;nt<4;nt++){
                int base=(nt*8+g)*72+ks*16+2*tg;
                unsigned bhf[2]={LDU(KhS,base),LDU(KhS,base+8)};
                unsigned blf[2]={LDU(KlS,base),LDU(KlS,base+8)};
                mma16816(sa[nt], qh[ks], bhf);
                mma16816(sa[nt], qh[ks], blf);
                mma16816(sa[nt], ql[ks], bhf);
            }
        }
        float ps[4][4];
        float mx0=-1e30f, mx1=-1e30f;
        #pragma unroll
        for(int nt=0;nt<4;nt++){
            int c0=k0+nt*8+2*tg, c1=c0+1;
            float s0=sa[nt][0]*0.125f; if(c0>row0) s0=-1e30f;
            float s1=sa[nt][1]*0.125f; if(c1>row0) s1=-1e30f;
            float s2=sa[nt][2]*0.125f; if(c0>row1) s2=-1e30f;
            float s3=sa[nt][3]*0.125f; if(c1>row1) s3=-1e30f;
            ps[nt][0]=s0; ps[nt][1]=s1; ps[nt][2]=s2; ps[nt][3]=s3;
            mx0=fmaxf(mx0,fmaxf(s0,s1)); mx1=fmaxf(mx1,fmaxf(s2,s3));
        }
        mx0=fmaxf(mx0,__shfl_xor_sync(0xffffffffu,mx0,1));
        mx0=fmaxf(mx0,__shfl_xor_sync(0xffffffffu,mx0,2));
        mx1=fmaxf(mx1,__shfl_xor_sync(0xffffffffu,mx1,1));
        mx1=fmaxf(mx1,__shfl_xor_sync(0xffffffffu,mx1,2));
        float mn0=fmaxf(m0,mx0), mn1=fmaxf(m1,mx1);
        float cr0=__expf(m0-mn0), cr1=__expf(m1-mn1);
        m0=mn0; m1=mn1;
        float sum0=0.f, sum1=0.f;
        #pragma unroll
        for(int nt=0;nt<4;nt++){
            ps[nt][0]=__expf(ps[nt][0]-mn0); ps[nt][1]=__expf(ps[nt][1]-mn0);
            ps[nt][2]=__expf(ps[nt][2]-mn1); ps[nt][3]=__expf(ps[nt][3]-mn1);
            sum0+=ps[nt][0]+ps[nt][1]; sum1+=ps[nt][2]+ps[nt][3];
        }
        sum0+=__shfl_xor_sync(0xffffffffu,sum0,1);
        sum0+=__shfl_xor_sync(0xffffffffu,sum0,2);
        sum1+=__shfl_xor_sync(0xffffffffu,sum1,1);
        sum1+=__shfl_xor_sync(0xffffffffu,sum1,2);
        l0=l0*cr0+sum0; l1=l1*cr1+sum1;
        #pragma unroll
        for(int ntv=0;ntv<8;ntv++){
            o[ntv][0]*=cr0; o[ntv][1]*=cr0; o[ntv][2]*=cr1; o[ntv][3]*=cr1;
        }
        #pragma unroll
        for(int ks2=0;ks2<2;ks2++){
            unsigned ah[4], al[4];
            split2(ps[2*ks2][0],  ps[2*ks2][1],  ah[0], al[0]);
            split2(ps[2*ks2][2],  ps[2*ks2][3],  ah[1], al[1]);
            split2(ps[2*ks2+1][0],ps[2*ks2+1][1],ah[2], al[2]);
            split2(ps[2*ks2+1][2],ps[2*ks2+1][3],ah[3], al[3]);
            #pragma unroll
            for(int ntv=0;ntv<8;ntv++){
                int base=(ntv*8+g)*40+ks2*16+2*tg;
                unsigned bhf[2]={LDU(VhS,base),LDU(VhS,base+8)};
                unsigned blf[2]={LDU(VlS,base),LDU(VlS,base+8)};
                mma16816(o[ntv], ah, bhf);
                mma16816(o[ntv], ah, blf);
                mma16816(o[ntv], al, bhf);
            }
        }
    }
    float i0=1.f/l0, i1=1.f/l1;
    float* yb=g_ys+(size_t)bh*Tn*Dn;
    #pragma unroll
    for(int ntv=0;ntv<8;ntv++){
        float2 w0; w0.x=o[ntv][0]*i0; w0.y=o[ntv][1]*i0;
        float2 w1; w1.x=o[ntv][2]*i1; w1.y=o[ntv][3]*i1;
        *(float2*)&yb[(size_t)row0*64+ntv*8+2*tg]=w0;
        *(float2*)&yb[(size_t)row1*64+ntv*8+2*tg]=w1;
    }
}

// ---------------- K3a: linear-attn chunk sums -----------------
__global__ __launch_bounds__(256) void k_lchunk()
{
    __shared__ __align__(16) float Kp[64*64];
    __shared__ __align__(16) float vv[64*64];
    const int tid=threadIdx.x, ch=blockIdx.x, bh=blockIdx.y, t0=ch*LCH;
    const float* kb=g_k+(size_t)bh*Tn*Dn;
    const float* vb=g_v+(size_t)bh*Tn*Dn;
    #pragma unroll
    for(int it=0;it<4;it++){
        int f=it*256+tid, t=f>>4, d4=(f&15)<<2;
        float4 k4=*(const float4*)&kb[(size_t)(t0+t)*64+d4];
        float4 kp; kp.x=elup(k4.x*0.125f); kp.y=elup(k4.y*0.125f); kp.z=elup(k4.z*0.125f); kp.w=elup(k4.w*0.125f);
        *(float4*)&Kp[t*64+d4]=kp;
        *(float4*)&vv[t*64+d4]=*(const float4*)&vb[(size_t)(t0+t)*64+d4];
    }
    __syncthreads();
    const int tx=tid&15, ty=tid>>4;
    float acc[4][4];
    #pragma unroll
    for(int i=0;i<4;i++) for(int j=0;j<4;j++) acc[i][j]=0.f;
    #pragma unroll 8
    for(int t=0;t<64;t++){
        float a0=Kp[t*64+ty*4], a1=Kp[t*64+ty*4+1], a2=Kp[t*64+ty*4+2], a3=Kp[t*64+ty*4+3];
        float b0=vv[t*64+tx*4], b1=vv[t*64+tx*4+1], b2=vv[t*64+tx*4+2], b3=vv[t*64+tx*4+3];
        acc[0][0]+=a0*b0; acc[0][1]+=a0*b1; acc[0][2]+=a0*b2; acc[0][3]+=a0*b3;
        acc[1][0]+=a1*b0; acc[1][1]+=a1*b1; acc[1][2]+=a1*b2; acc[1][3]+=a1*b3;
        acc[2][0]+=a2*b0; acc[2][1]+=a2*b1; acc[2][2]+=a2*b2; acc[2][3]+=a2*b3;
        acc[3][0]+=a3*b0; acc[3][1]+=a3*b1; acc[3][2]+=a3*b2; acc[3][3]+=a3*b3;
    }
    float* st=g_st+(size_t)(bh*NCH+ch)*4096;
    #pragma unroll
    for(int i=0;i<4;i++) for(int j=0;j<4;j++) st[(ty*4+i)*64+tx*4+j]=acc[i][j];
    if(tid<64){
        float s=0.f;
        #pragma unroll 8
        for(int t=0;t<64;t++) s+=Kp[t*64+tid];
        g_ks[(bh*NCH+ch)*64+tid]=s;
    }
}

// ---------------- K3b: exclusive scan over chunks (one chain per thread) --------
__global__ __launch_bounds__(256) void k_lscan()
{
    const int bh=blockIdx.x, e=blockIdx.y*256+threadIdx.x;
    float run=0.f;
    #pragma unroll
    for(int ch=0;ch<NCH;ch++){
        float* p=&g_st[(size_t)(bh*NCH+ch)*4096+e];
        float tv=*p; *p=run; run+=tv;
    }
    if(blockIdx.y==0 && threadIdx.x<64){
        float r2=0.f;
        #pragma unroll
        for(int ch=0;ch<NCH;ch++){
            float* p=&g_ks[(bh*NCH+ch)*64+threadIdx.x];
            float tv=*p; *p=r2; r2+=tv;
        }
    }
}

// ---------------- K3c: linear-attn output -----------------
__global__ __launch_bounds__(256) void k_lout()
{
    __shared__ __align__(16) float bufQ[64*64];
    __shared__ float bufA[64*65];
    __shared__ float ks0[64], den[64];
    const int tid=threadIdx.x, ch=blockIdx.x, bh=blockIdx.y, t0=ch*LCH;
    const int tx=tid&15, ty=tid>>4;
    const float* qb=g_q+(size_t)bh*Tn*Dn;
    const float* kb=g_k+(size_t)bh*Tn*Dn;
    const float* vb=g_v+(size_t)bh*Tn*Dn;
    const float* S0=g_st+(size_t)(bh*NCH+ch)*4096;
    #pragma unroll
    for(int it=0;it<4;it++){
        int f=it*256+tid, t=f>>4, d4=(f&15)<<2;
        float4 q4=*(const float4*)&qb[(size_t)(t0+t)*64+d4];
        float4 qp; qp.x=elup(q4.x*0.125f); qp.y=elup(q4.y*0.125f); qp.z=elup(q4.z*0.125f); qp.w=elup(q4.w*0.125f);
        *(float4*)&bufQ[t*64+d4]=qp;
        float4 k4=*(const float4*)&kb[(size_t)(t0+t)*64+d4];
        bufA[t*65+d4]=elup(k4.x*0.125f); bufA[t*65+d4+1]=elup(k4.y*0.125f);
        bufA[t*65+d4+2]=elup(k4.z*0.125f); bufA[t*65+d4+3]=elup(k4.w*0.125f);
    }
    if(tid<64) ks0[tid]=g_ks[(bh*NCH+ch)*64+tid];
    __syncthreads();
    float A4[4][4], o[4][4];
    #pragma unroll
    for(int i=0;i<4;i++) for(int j=0;j<4;j++){ A4[i][j]=0.f; o[i][j]=0.f; }
    #pragma unroll 4
    for(int d=0;d<64;d++){
        float a0=bufQ[(ty*4+0)*64+d], a1=bufQ[(ty*4+1)*64+d];
        float a2=bufQ[(ty*4+2)*64+d], a3=bufQ[(ty*4+3)*64+d];
        float b0=bufA[(tx*4+0)*65+d], b1=bufA[(tx*4+1)*65+d];
        float b2=bufA[(tx*4+2)*65+d], b3=bufA[(tx*4+3)*65+d];
        A4[0][0]+=a0*b0; A4[0][1]+=a0*b1; A4[0][2]+=a0*b2; A4[0][3]+=a0*b3;
        A4[1][0]+=a1*b0; A4[1][1]+=a1*b1; A4[1][2]+=a1*b2; A4[1][3]+=a1*b3;
        A4[2][0]+=a2*b0; A4[2][1]+=a2*b1; A4[2][2]+=a2*b2; A4[2][3]+=a2*b3;
        A4[3][0]+=a3*b0; A4[3][1]+=a3*b1; A4[3][2]+=a3*b2; A4[3][3]+=a3*b3;
        float4 s4=*(const float4*)&S0[d*64+tx*4];
        o[0][0]+=a0*s4.x; o[0][1]+=a0*s4.y; o[0][2]+=a0*s4.z; o[0][3]+=a0*s4.w;
        o[1][0]+=a1*s4.x; o[1][1]+=a1*s4.y; o[1][2]+=a1*s4.z; o[1][3]+=a1*s4.w;
        o[2][0]+=a2*s4.x; o[2][1]+=a2*s4.y; o[2][2]+=a2*s4.z; o[2][3]+=a2*s4.w;
        o[3][0]+=a3*s4.x; o[3][1]+=a3*s4.y; o[3][2]+=a3*s4.z; o[3][3]+=a3*s4.w;
    }
    __syncthreads();
    #pragma unroll
    for(int i=0;i<4;i++) for(int j=0;j<4;j++){
        int t=ty*4+i, s=tx*4+j;
        bufA[t*65+s] = (s<=t)? A4[i][j] : 0.f;
    }
    __syncthreads();
    if(tid<64){
        float dsum=0.f;
        #pragma unroll 8
        for(int s=0;s<64;s++) dsum+=bufA[tid*65+s];
        #pragma unroll 8
        for(int d=0;d<64;d++) dsum+=bufQ[tid*64+d]*ks0[d];
        den[tid]=dsum;
    }
    #pragma unroll 4
    for(int s=0;s<64;s++){
        float a0=bufA[(ty*4+0)*65+s], a1=bufA[(ty*4+1)*65+s];
        float a2=bufA[(ty*4+2)*65+s], a3=bufA[(ty*4+3)*65+s];
        float4 v4=*(const float4*)&vb[(size_t)(t0+s)*64+tx*4];
        o[0][0]+=a0*v4.x; o[0][1]+=a0*v4.y; o[0][2]+=a0*v4.z; o[0][3]+=a0*v4.w;
        o[1][0]+=a1*v4.x; o[1][1]+=a1*v4.y; o[1][2]+=a1*v4.z; o[1][3]+=a1*v4.w;
        o[2][0]+=a2*v4.x; o[2][1]+=a2*v4.y; o[2][2]+=a2*v4.z; o[2][3]+=a2*v4.w;
        o[3][0]+=a3*v4.x; o[3][1]+=a3*v4.y; o[3][2]+=a3*v4.z; o[3][3]+=a3*v4.w;
    }
    __syncthreads();
    float* yb=g_yl+(size_t)bh*Tn*Dn;
    #pragma unroll
    for(int i=0;i<4;i++){
        float inv=1.f/(den[ty*4+i]+1e-4f);
        #pragma unroll
        for(int j=0;j<4;j++) yb[(size_t)(t0+ty*4+i)*64+tx*4+j]=o[i][j]*inv;
    }
}

// ---------------- K4: epilogue megakernel -----------------
__device__ __forceinline__ void bred2(float& s, float& ss, float* scr, int tid){
    #pragma unroll
    for(int off=16;off>0;off>>=1){
        s += __shfl_xor_sync(0xffffffffu, s, off);
        ss+= __shfl_xor_sync(0xffffffffu, ss, off);
    }
    int w=tid>>5;
    if((tid&31)==0){ scr[w]=s; scr[8+w]=ss; }
    __syncthreads();
    if(tid<8){ s=scr[tid]; ss=scr[8+tid]; }
    else { s=0.f; ss=0.f; }
    if(tid<32){
        #pragma unroll
        for(int off=4;off>0;off>>=1){
            s += __shfl_xor_sync(0xffffffffu, s, off);
            ss+= __shfl_xor_sync(0xffffffffu, ss, off);
        }
        if(tid==0){ scr[16]=s; scr[17]=ss; }
    }
    __syncthreads();
    s=scr[16]; ss=scr[17];
    __syncthreads();
}

__global__ __launch_bounds__(256) void k_epi(
    const float* __restrict__ fg,
    const float* __restrict__ ang, const float* __restrict__ anb,
    const float* __restrict__ ong, const float* __restrict__ onb,
    const float* __restrict__ pg,  const float* __restrict__ pb,
    const float* __restrict__ bw,  const float* __restrict__ wrow,
    const float* __restrict__ wcol,const float* __restrict__ pa_,
    const float* __restrict__ pbias, float* __restrict__ out)
{
    __shared__ float yv[1024];
    __shared__ float xn[1024];
    __shared__ float z[32*33];
    __shared__ float scr[18];
    const int tid=threadIdx.x;
    const int bt=blockIdx.x, b=bt>>10, t=bt&1023;
    const float alpha=1.f/(1.f+__expf(-fg[0]));
    const float pav=pa_[0];
    {
        int h=tid>>4, l=tid&15, d0=l*4;
        size_t base=(((size_t)(b*Hn+h))*Tn+t)*Dn;
        float4 v4=*(const float4*)&g_yl[base+d0];
        float s=v4.x+v4.y+v4.z+v4.w;
        float ss=v4.x*v4.x+v4.y*v4.y+v4.z*v4.z+v4.w*v4.w;
        #pragma unroll
        for(int off=8;off>0;off>>=1){
            s += __shfl_xor_sync(0xffffffffu, s, off, 16);
            ss+= __shfl_xor_sync(0xffffffffu, ss, off, 16);
        }
        float m=s*(1.f/64.f), var=ss*(1.f/64.f)-m*m;
        float rs=rsqrtf(var+1e-5f);
        float4 s4=*(const float4*)&g_ys[base+d0];
        float r[4]={v4.x,v4.y,v4.z,v4.w}, sh[4]={s4.x,s4.y,s4.z,s4.w};
        #pragma unroll
        for(int q=0;q<4;q++){
            float ln=(r[q]-m)*rs*ang[d0+q]+anb[d0+q];
            yv[h*64+d0+q]=alpha*sh[q]+(1.f-alpha)*ln;
        }
    }
    __syncthreads();
    {
        float s=0.f, ss=0.f;
        #pragma unroll
        for(int q=0;q<4;q++){ float v=yv[tid*4+q]; s+=v; ss+=v*v; }
        bred2(s,ss,scr,tid);
        float m=s*(1.f/1024.f), var=ss*(1.f/1024.f)-m*m, rs=rsqrtf(var+1e-5f);
        #pragma unroll
        for(int q=0;q<4;q++){
            int c=tid*4+q;
            yv[c]=(yv[c]-m)*rs*ong[c]+onb[c];
        }
    }
    __syncthreads();
    {
        float s=0.f, ss=0.f;
        #pragma unroll
        for(int q=0;q<4;q++){ float v=yv[tid*4+q]; s+=v; ss+=v*v; }
        bred2(s,ss,scr,tid);
        float m=s*(1.f/1024.f), var=ss*(1.f/1024.f)-m*m, rs=rsqrtf(var+1e-5f);
        #pragma unroll
        for(int q=0;q<4;q++){
            int c=tid*4+q;
            xn[c]=(yv[c]-m)*rs*pg[c]+pb[c];
        }
    }
    __syncthreads();
    #pragma unroll
    for(int q=0;q<4;q++){
        int p=tid*4+q, i=p>>5, c=p&31;
        float acc=0.f;
        #pragma unroll 8
        for(int j=0;j<32;j++) acc+=xn[i*32+j]*wcol[j*32+c];
        z[i*33+c]=acc;
    }
    __syncthreads();
    float* orow=out+(size_t)bt*1024;
    #pragma unroll
    for(int q=0;q<4;q++){
        int p=tid*4+q;
        int mrev=1023-p, gm=mrev>>4, jj=mrev&15;
        float bo=0.f;
        #pragma unroll
        for(int i=0;i<16;i++) bo+=xn[gm*16+i]*bw[(gm*16+i)*16+jj];
        int gi=p>>5, r=p&31;
        float zz=0.f;
        #pragma unroll 8
        for(int c=0;c<32;c++) zz+=z[gi*33+c]*wrow[r*32+c];
        orow[p]=bo+pav*zz+pbias[p];
    }
}

extern "C" void kernel_launch(void* const* d_in, const int* in_sizes, int n_in,
                              void* d_out, int out_size)
{
    const float* x    =(const float*)d_in[0];
    const float* caw  =(const float*)d_in[1];
    const float* cab  =(const float*)d_in[2];
    const float* fg   =(const float*)d_in[3];
    const float* ang  =(const float*)d_in[4];
    const float* anb  =(const float*)d_in[5];
    const float* ong  =(const float*)d_in[6];
    const float* onb  =(const float*)d_in[7];
    const float* ppg  =(const float*)d_in[8];
    const float* ppb  =(const float*)d_in[9];
    const float* pbw  =(const float*)d_in[10];
    const float* pwr  =(const float*)d_in[11];
    const float* pwc  =(const float*)d_in[12];
    const float* pal  =(const float*)d_in[13];
    const float* pbi  =(const float*)d_in[14];
    float* out=(float*)d_out;

    k_cvt1<<<5120,256>>>(x,caw);
    k_qkv<<<dim3(24,16),256>>>(cab);
    k_cvt2<<<dim3(32,16),256>>>();
    k_attn<<<dim3(8,32),256>>>();
    k_lchunk<<<dim3(NCH,32),256>>>();
    k_lscan<<<dim3(32,16),256>>>();
    k_lout<<<dim3(NCH,32),256>>>();
    k_epi<<<2048,256>>>(fg,ang,anb,ong,onb,ppg,ppb,pbw,pwr,pwc,pal,pbi,out);
}